// round 13
// baseline (speedup 1.0000x reference)
#include <cuda_runtime.h>
#include <cuda_bf16.h>
#include <math.h>
#include <stdint.h>

// Problem constants
#define NB 16384
#define ND 1024
#define NE 8
#define NH 512
#define NT 256
#define NTASK 3

// GEMM tiling (bf16 mma.sync m16n8k16)
#define TM 128
#define TN 128
#define BK 64
#define NSTAGE 3
#define STAGE_BYTES 16384             // 128 rows x 128 B (64 bf16)
#define OFF_B (NSTAGE * STAGE_BYTES)  // 49152
#define OFF_BIAS (2 * NSTAGE * STAGE_BYTES)   // 98304
#define SMEM_BYTES (OFF_BIAS + 512)   // 98816 -> 2 CTAs/SM

// Tower kernel extra smem (on top of the GEMM layout)
#define TW_OFF_W2   (OFF_BIAS + 512)          // 128 floats
#define TW_OFF_PART (TW_OFF_W2 + 512)         // 2 x 128 floats
#define TW_SMEM     (TW_OFF_PART + 1024)      // 100352 -> still 2 CTAs/SM

// Gates kernel smem: 24 rows x 1032 floats
#define WG_PITCH 1032
#define GATES_SMEM (NTASK * NE * WG_PITCH * 4)

// M-tiles per expert-GEMM CTA (flat pipelined)
#define MTILES 2

// ---------------------------------------------------------------------------
// Scratch (device globals; no runtime allocation allowed)
// ---------------------------------------------------------------------------
__device__ __nv_bfloat16 g_xb[(size_t)NB * ND];            // x in bf16
__device__ __nv_bfloat16 g_h1b[(size_t)NE * NB * NH];      // [E,B,H] bf16
__device__ __nv_bfloat16 g_eob[(size_t)NE * NB * NH];      // [E,B,H] bf16
__device__ __nv_bfloat16 g_tinb[(size_t)NTASK * NB * NH];  // [T,B,H] bf16
__device__ float g_gates[(size_t)NTASK * NB * NE];         // [T,B,E]
__device__ float g_part[(size_t)NTASK * 2 * NB];           // tower head partials
__device__ __nv_bfloat16 g_We1T[(size_t)NE * NH * ND];     // [E,H,D] bf16 NK
__device__ __nv_bfloat16 g_We2T[(size_t)NE * NH * NH];     // [E,H,H]
__device__ __nv_bfloat16 g_Wt1T[(size_t)NTASK * NT * NH];  // [T,NT,H]

// ---------------------------------------------------------------------------
// Helpers (sm_80-class PTX only)
// ---------------------------------------------------------------------------
__device__ __forceinline__ uint32_t smem_u32(const void* p) {
    uint32_t a;
    asm("{ .reg .u64 t; cvta.to.shared.u64 t, %1; cvt.u32.u64 %0, t; }" : "=r"(a) : "l"(p));
    return a;
}

#define CP_ASYNC16(dst, src) \
    asm volatile("cp.async.cg.shared.global [%0], [%1], 16;" :: "r"(dst), "l"(src))
#define CP_COMMIT() asm volatile("cp.async.commit_group;" ::: "memory")
#define CP_WAIT1()  asm volatile("cp.async.wait_group 1;" ::: "memory")
#define CP_WAIT0()  asm volatile("cp.async.wait_group 0;" ::: "memory")

__device__ __forceinline__ void ldmatrix_x4(uint32_t& r0, uint32_t& r1,
                                            uint32_t& r2, uint32_t& r3, uint32_t addr) {
    asm volatile("ldmatrix.sync.aligned.m8n8.x4.shared.b16 {%0,%1,%2,%3}, [%4];"
                 : "=r"(r0), "=r"(r1), "=r"(r2), "=r"(r3) : "r"(addr));
}

__device__ __forceinline__ void mma_bf16(float (&d)[4], const uint32_t (&a)[4],
                                         const uint32_t (&b)[2]) {
    asm volatile(
        "mma.sync.aligned.m16n8k16.row.col.f32.bf16.bf16.f32 "
        "{%0,%1,%2,%3}, {%4,%5,%6,%7}, {%8,%9}, {%0,%1,%2,%3};"
        : "+f"(d[0]), "+f"(d[1]), "+f"(d[2]), "+f"(d[3])
        : "r"(a[0]), "r"(a[1]), "r"(a[2]), "r"(a[3]), "r"(b[0]), "r"(b[1]));
}

__device__ __forceinline__ uint32_t sw128(uint32_t off) {
    return off ^ ((off >> 3) & 0x70);
}

// ---------------------------------------------------------------------------
// Merged prep: weight transposes (bf16) + x fp32->bf16 convert, one launch.
// bid < 6528: transpose tiles; bid >= 6528: f2b blocks.
// ---------------------------------------------------------------------------
__global__ __launch_bounds__(256)
void prep_all_kernel(const float* __restrict__ We1, __nv_bfloat16* __restrict__ We1T,
                     const float* __restrict__ We2, __nv_bfloat16* __restrict__ We2T,
                     const float* __restrict__ Wt1, __nv_bfloat16* __restrict__ Wt1T,
                     const float* __restrict__ x,   __nv_bfloat16* __restrict__ xb)
{
    const int bid = blockIdx.x;
    if (bid >= 6528) {
        // f2b: 16384 blocks x 256 threads x 1 float4
        const int i = (bid - 6528) * 256 + threadIdx.x;
        float4 v = ((const float4*)x)[i];
        __nv_bfloat162* o = (__nv_bfloat162*)xb + (size_t)i * 2;
        o[0] = __floats2bfloat162_rn(v.x, v.y);
        o[1] = __floats2bfloat162_rn(v.z, v.w);
        return;
    }

    __shared__ float t[32][33];
    const float* in;
    __nv_bfloat16* out;
    int K, N, z, ky, nx;
    if (bid < 4096) {                    // We1: z=8, K=1024, N=512
        const int r = bid;
        z = r >> 9; const int tt = r & 511;
        ky = tt >> 4; nx = tt & 15;
        K = ND; N = NH; in = We1; out = We1T;
    } else if (bid < 6144) {             // We2: z=8, K=512, N=512
        const int r = bid - 4096;
        z = r >> 8; const int tt = r & 255;
        ky = tt >> 4; nx = tt & 15;
        K = NH; N = NH; in = We2; out = We2T;
    } else {                             // Wt1: z=3, K=512, N=256
        const int r = bid - 6144;
        z = r >> 7; const int tt = r & 127;
        ky = tt >> 3; nx = tt & 7;
        K = NH; N = NT; in = Wt1; out = Wt1T;
    }
    in  += (size_t)z * K * N;
    out += (size_t)z * K * N;
    const int k0 = ky * 32, n0 = nx * 32;
    const int tx = threadIdx.x & 31, ty = threadIdx.x >> 5;
#pragma unroll
    for (int i = 0; i < 32; i += 8)
        t[ty + i][tx] = in[(size_t)(k0 + ty + i) * N + n0 + tx];
    __syncthreads();
#pragma unroll
    for (int i = 0; i < 32; i += 8)
        out[(size_t)(n0 + ty + i) * K + k0 + tx] = __float2bfloat16_rn(t[tx][ty + i]);
}

// ---------------------------------------------------------------------------
// Gates kernel (forked stream): x.Wg + softmax, 4 rows per thread.
// ---------------------------------------------------------------------------
__global__ __launch_bounds__(256)
void gates_kernel(const float* __restrict__ x, const float* __restrict__ Wg,
                  const float* __restrict__ bg, float* __restrict__ gates)
{
    extern __shared__ float wg_s[];   // [24][WG_PITCH]
    const int tid = threadIdx.x;

    for (int i = tid; i < NTASK * ND * NE / 4; i += 256) {
        const float4 v = ((const float4*)Wg)[i];
        const int base = i * 4;
        const int tt = base / (ND * NE);
        const int r  = base - tt * (ND * NE);
        const int d  = r >> 3;
        const int e0 = r & 7;
        wg_s[(tt * NE + e0 + 0) * WG_PITCH + d] = v.x;
        wg_s[(tt * NE + e0 + 1) * WG_PITCH + d] = v.y;
        wg_s[(tt * NE + e0 + 2) * WG_PITCH + d] = v.z;
        wg_s[(tt * NE + e0 + 3) * WG_PITCH + d] = v.w;
    }
    __syncthreads();

    const int wid = tid >> 5, lane = tid & 31;
    const int b0 = blockIdx.x * 32 + wid * 4;

    const float4* xr0 = (const float4*)(x + (size_t)(b0 + 0) * ND);
    const float4* xr1 = (const float4*)(x + (size_t)(b0 + 1) * ND);
    const float4* xr2 = (const float4*)(x + (size_t)(b0 + 2) * ND);
    const float4* xr3 = (const float4*)(x + (size_t)(b0 + 3) * ND);

    float acc[4][24];
#pragma unroll
    for (int r = 0; r < 4; r++)
#pragma unroll
        for (int te = 0; te < 24; te++) acc[r][te] = 0.f;

#pragma unroll
    for (int i = 0; i < 8; i++) {
        const int d4 = lane + 32 * i;
        float4 xv[4];
        xv[0] = xr0[d4]; xv[1] = xr1[d4]; xv[2] = xr2[d4]; xv[3] = xr3[d4];
#pragma unroll
        for (int te = 0; te < 24; te++) {
            const float4 wv = *(const float4*)(wg_s + te * WG_PITCH + d4 * 4);
#pragma unroll
            for (int r = 0; r < 4; r++) {
                acc[r][te] += xv[r].x * wv.x + xv[r].y * wv.y +
                              xv[r].z * wv.z + xv[r].w * wv.w;
            }
        }
    }
#pragma unroll
    for (int off = 16; off > 0; off >>= 1)
#pragma unroll
        for (int r = 0; r < 4; r++)
#pragma unroll
            for (int te = 0; te < 24; te++)
                acc[r][te] += __shfl_xor_sync(0xffffffffu, acc[r][te], off);

    if (lane < NTASK) {
        const int t = lane;
#pragma unroll
        for (int r = 0; r < 4; r++) {
            float v[NE];
            float mx = -1e30f;
#pragma unroll
            for (int e = 0; e < NE; e++) {
                v[e] = acc[r][t * NE + e] + bg[t * NE + e];
                mx = fmaxf(mx, v[e]);
            }
            float s = 0.f;
#pragma unroll
            for (int e = 0; e < NE; e++) { v[e] = expf(v[e] - mx); s += v[e]; }
            const float inv = 1.f / s;
            float* gout = gates + ((size_t)t * NB + b0 + r) * NE;
#pragma unroll
            for (int e = 0; e < NE; e++) gout[e] = v[e] * inv;
        }
    }
}

// ---------------------------------------------------------------------------
// bf16 tensor-core batched GEMM (expert layers): C = relu(A @ Bt^T + bias)
// CTA tile 128x128, BK=64, 3-stage cp.async, 4 warps, 64x64 warp tiles.
// Each CTA processes MTILES consecutive M-tiles in ONE flat software pipeline
// (loads for the next tile are in flight during the previous tile's epilogue).
// grid = (N/TN, M/(TM*MTILES), E).
// ---------------------------------------------------------------------------
__global__ __launch_bounds__(128, 2)
void gemm_bf16_kernel(const __nv_bfloat16* __restrict__ Ab,
                      const __nv_bfloat16* __restrict__ Bb,
                      const float* __restrict__ biasb, __nv_bfloat16* __restrict__ Cb,
                      int K, int ldc,
                      long long sA, long long sB, long long sBias, long long sC)
{
    extern __shared__ char dynsmem[];
    const uint32_t smb = smem_u32(dynsmem);

    const int z = blockIdx.z;
    const __nv_bfloat16* Abase = Ab + (size_t)z * sA +
                                 (size_t)(blockIdx.y * (TM * MTILES)) * K;
    const __nv_bfloat16* Bt = Bb + (size_t)z * sB + (size_t)(blockIdx.x * TN) * K;
    const float* bias = biasb + (size_t)z * sBias + blockIdx.x * TN;
    __nv_bfloat16* Cbase = Cb + (size_t)z * sC +
                           (size_t)(blockIdx.y * (TM * MTILES)) * ldc + blockIdx.x * TN;

    const int tid   = threadIdx.x;
    const int wid   = tid >> 5;
    const int lane  = tid & 31;
    const int gid   = lane >> 2;
    const int tig   = lane & 3;
    const int warpM = wid >> 1;
    const int warpN = wid & 1;

    float* bias_s = (float*)(dynsmem + OFF_BIAS);
    if (tid < TN) bias_s[tid] = bias[tid];

    const int ns = K / BK;
    const int total = MTILES * ns;

    // flat stage loader: f -> (tile = f/ns, s = f%ns)
    auto load_stage = [&](int f, int buf) {
        const int t = f / ns;
        const int s = f - t * ns;
        const __nv_bfloat16* Ag = Abase + (size_t)(t * TM) * K + s * BK;
        const __nv_bfloat16* Bg = Bt + s * BK;
#pragma unroll
        for (int i = 0; i < 8; i++) {
            const int idx = tid + i * 128;
            const int row = idx >> 3;
            const int c8  = idx & 7;
            const uint32_t off = sw128((uint32_t)(row * 128 + c8 * 16));
            CP_ASYNC16(smb + buf * STAGE_BYTES + off, Ag + (size_t)row * K + c8 * 8);
            CP_ASYNC16(smb + OFF_B + buf * STAGE_BYTES + off, Bg + (size_t)row * K + c8 * 8);
        }
        CP_COMMIT();
    };

    float acc[4][8][4];
#pragma unroll
    for (int mt = 0; mt < 4; mt++)
#pragma unroll
        for (int nt = 0; nt < 8; nt++)
#pragma unroll
            for (int r = 0; r < 4; r++) acc[mt][nt][r] = 0.f;

    const int a_row  = warpM * 64 + (lane & 15);
    const int a_koff = (lane >> 4) * 16;
    const int b_row  = warpN * 64 + (lane & 7) + ((lane >> 4) << 3);
    const int b_koff = ((lane >> 3) & 1) * 16;

    uint32_t af[2][4][4];
    uint32_t bf[2][8][2];

    load_stage(0, 0);
    load_stage(1, 1);

    for (int f = 0; f < total; f++) {
        if (f + 1 < total) CP_WAIT1(); else CP_WAIT0();
        __syncthreads();   // single barrier per stage (fences (f+2)%3 reuse too)

        const int buf = f % NSTAGE;
        const uint32_t sa = smb + buf * STAGE_BYTES;
        const uint32_t sb = smb + OFF_B + buf * STAGE_BYTES;

        // fragments for kk=0
#pragma unroll
        for (int mt = 0; mt < 4; mt++) {
            const uint32_t off = (uint32_t)((a_row + mt * 16) * 128 + a_koff);
            ldmatrix_x4(af[0][mt][0], af[0][mt][1], af[0][mt][2], af[0][mt][3],
                        sa + sw128(off));
        }
#pragma unroll
        for (int pr = 0; pr < 4; pr++) {
            const uint32_t off = (uint32_t)((b_row + pr * 16) * 128 + b_koff);
            ldmatrix_x4(bf[0][pr * 2][0], bf[0][pr * 2][1],
                        bf[0][pr * 2 + 1][0], bf[0][pr * 2 + 1][1], sb + sw128(off));
        }

#pragma unroll
        for (int kk = 0; kk < 4; kk++) {
            const int cur = kk & 1;
            const int nxt = cur ^ 1;
            if (kk < 3) {
#pragma unroll
                for (int mt = 0; mt < 4; mt++) {
                    const uint32_t off =
                        (uint32_t)((a_row + mt * 16) * 128 + (kk + 1) * 32 + a_koff);
                    ldmatrix_x4(af[nxt][mt][0], af[nxt][mt][1], af[nxt][mt][2],
                                af[nxt][mt][3], sa + sw128(off));
                }
#pragma unroll
                for (int pr = 0; pr < 4; pr++) {
                    const uint32_t off =
                        (uint32_t)((b_row + pr * 16) * 128 + (kk + 1) * 32 + b_koff);
                    ldmatrix_x4(bf[nxt][pr * 2][0], bf[nxt][pr * 2][1],
                                bf[nxt][pr * 2 + 1][0], bf[nxt][pr * 2 + 1][1],
                                sb + sw128(off));
                }
            }
#pragma unroll
            for (int mt = 0; mt < 4; mt++)
#pragma unroll
                for (int nt = 0; nt < 8; nt++)
                    mma_bf16(acc[mt][nt], af[cur][mt], bf[cur][nt]);
        }
        if (f + 2 < total) load_stage(f + 2, (f + 2) % NSTAGE);

        // Tile boundary: epilogue (registers + read-only bias_s; no sync needed).
        if ((f + 1) % ns == 0) {
            const int t = f / ns;
            __nv_bfloat16* C = Cbase + (size_t)(t * TM) * ldc;
#pragma unroll
            for (int mt = 0; mt < 4; mt++) {
                const int r0 = warpM * 64 + mt * 16 + gid;
#pragma unroll
                for (int nt = 0; nt < 8; nt++) {
                    const int c = warpN * 64 + nt * 8 + tig * 2;
                    const float2 bv = *(const float2*)(bias_s + c);
                    float v0 = fmaxf(acc[mt][nt][0] + bv.x, 0.f);
                    float v1 = fmaxf(acc[mt][nt][1] + bv.y, 0.f);
                    float v2 = fmaxf(acc[mt][nt][2] + bv.x, 0.f);
                    float v3 = fmaxf(acc[mt][nt][3] + bv.y, 0.f);
                    *(__nv_bfloat162*)(C + (size_t)r0 * ldc + c) =
                        __floats2bfloat162_rn(v0, v1);
                    *(__nv_bfloat162*)(C + (size_t)(r0 + 8) * ldc + c) =
                        __floats2bfloat162_rn(v2, v3);
                    acc[mt][nt][0] = 0.f; acc[mt][nt][1] = 0.f;
                    acc[mt][nt][2] = 0.f; acc[mt][nt][3] = 0.f;
                }
            }
        }
    }
}

// ---------------------------------------------------------------------------
// Tower GEMM with fused head-partial epilogue. grid = (2, NB/128, NTASK).
// ---------------------------------------------------------------------------
__global__ __launch_bounds__(128, 2)
void tower_gemm_kernel(const __nv_bfloat16* __restrict__ tin,
                       const __nv_bfloat16* __restrict__ Wt1T,
                       const float* __restrict__ bt1,
                       const float* __restrict__ Wt2,
                       float* __restrict__ part)
{
    extern __shared__ char dynsmem[];
    const uint32_t smb = smem_u32(dynsmem);
    const int K = NH;

    const int z = blockIdx.z;
    const __nv_bfloat16* A  = tin + (size_t)z * NB * NH + (size_t)(blockIdx.y * TM) * K;
    const __nv_bfloat16* Bt = Wt1T + (size_t)z * NT * NH + (size_t)(blockIdx.x * TN) * K;

    const int tid   = threadIdx.x;
    const int wid   = tid >> 5;
    const int lane  = tid & 31;
    const int gid   = lane >> 2;
    const int tig   = lane & 3;
    const int warpM = wid >> 1;
    const int warpN = wid & 1;

    float* bias_s = (float*)(dynsmem + OFF_BIAS);
    float* w2_s   = (float*)(dynsmem + TW_OFF_W2);
    float* part_s = (float*)(dynsmem + TW_OFF_PART);  // [2][128]
    if (tid < TN) {
        bias_s[tid] = bt1[z * NT + blockIdx.x * TN + tid];
        w2_s[tid]   = Wt2[z * NT + blockIdx.x * TN + tid];
    }

    auto load_stage = [&](int buf, int k0) {
        const __nv_bfloat16* Ag = A + k0;
        const __nv_bfloat16* Bg = Bt + k0;
#pragma unroll
        for (int i = 0; i < 8; i++) {
            const int idx = tid + i * 128;
            const int row = idx >> 3;
            const int c8  = idx & 7;
            const uint32_t off = sw128((uint32_t)(row * 128 + c8 * 16));
            CP_ASYNC16(smb + buf * STAGE_BYTES + off, Ag + (size_t)row * K + c8 * 8);
            CP_ASYNC16(smb + OFF_B + buf * STAGE_BYTES + off, Bg + (size_t)row * K + c8 * 8);
        }
        CP_COMMIT();
    };

    float acc[4][8][4];
#pragma unroll
    for (int mt = 0; mt < 4; mt++)
#pragma unroll
        for (int nt = 0; nt < 8; nt++)
#pragma unroll
            for (int r = 0; r < 4; r++) acc[mt][nt][r] = 0.f;

    const int a_row  = warpM * 64 + (lane & 15);
    const int a_koff = (lane >> 4) * 16;
    const int b_row  = warpN * 64 + (lane & 7) + ((lane >> 4) << 3);
    const int b_koff = ((lane >> 3) & 1) * 16;

    uint32_t af[2][4][4];
    uint32_t bf[2][8][2];

    const int ns = K / BK;      // 8
    load_stage(0, 0);
    load_stage(1, BK);

    for (int s = 0; s < ns; s++) {
        if (s + 1 < ns) CP_WAIT1(); else CP_WAIT0();
        __syncthreads();

        const int buf = s % NSTAGE;
        const uint32_t sa = smb + buf * STAGE_BYTES;
        const uint32_t sb = smb + OFF_B + buf * STAGE_BYTES;

#pragma unroll
        for (int mt = 0; mt < 4; mt++) {
            const uint32_t off = (uint32_t)((a_row + mt * 16) * 128 + a_koff);
            ldmatrix_x4(af[0][mt][0], af[0][mt][1], af[0][mt][2], af[0][mt][3],
                        sa + sw128(off));
        }
#pragma unroll
        for (int pr = 0; pr < 4; pr++) {
            const uint32_t off = (uint32_t)((b_row + pr * 16) * 128 + b_koff);
            ldmatrix_x4(bf[0][pr * 2][0], bf[0][pr * 2][1],
                        bf[0][pr * 2 + 1][0], bf[0][pr * 2 + 1][1], sb + sw128(off));
        }

#pragma unroll
        for (int kk = 0; kk < 4; kk++) {
            const int cur = kk & 1;
            const int nxt = cur ^ 1;
            if (kk < 3) {
#pragma unroll
                for (int mt = 0; mt < 4; mt++) {
                    const uint32_t off =
                        (uint32_t)((a_row + mt * 16) * 128 + (kk + 1) * 32 + a_koff);
                    ldmatrix_x4(af[nxt][mt][0], af[nxt][mt][1], af[nxt][mt][2],
                                af[nxt][mt][3], sa + sw128(off));
                }
#pragma unroll
                for (int pr = 0; pr < 4; pr++) {
                    const uint32_t off =
                        (uint32_t)((b_row + pr * 16) * 128 + (kk + 1) * 32 + b_koff);
                    ldmatrix_x4(bf[nxt][pr * 2][0], bf[nxt][pr * 2][1],
                                bf[nxt][pr * 2 + 1][0], bf[nxt][pr * 2 + 1][1],
                                sb + sw128(off));
                }
            }
#pragma unroll
            for (int mt = 0; mt < 4; mt++)
#pragma unroll
                for (int nt = 0; nt < 8; nt++)
                    mma_bf16(acc[mt][nt], af[cur][mt], bf[cur][nt]);
        }
        if (s + 2 < ns) load_stage((s + 2) % NSTAGE, (s + 2) * BK);
    }

    // Fused head-partial epilogue.
#pragma unroll
    for (int mt = 0; mt < 4; mt++) {
        float p0 = 0.f, p1 = 0.f;
#pragma unroll
        for (int nt = 0; nt < 8; nt++) {
            const int c = warpN * 64 + nt * 8 + tig * 2;
            const float b0 = bias_s[c], b1 = bias_s[c + 1];
            const float w0 = w2_s[c],  w1 = w2_s[c + 1];
            p0 += fmaxf(acc[mt][nt][0] + b0, 0.f) * w0 + fmaxf(acc[mt][nt][1] + b1, 0.f) * w1;
            p1 += fmaxf(acc[mt][nt][2] + b0, 0.f) * w0 + fmaxf(acc[mt][nt][3] + b1, 0.f) * w1;
        }
        p0 += __shfl_xor_sync(0xffffffffu, p0, 1);
        p0 += __shfl_xor_sync(0xffffffffu, p0, 2);
        p1 += __shfl_xor_sync(0xffffffffu, p1, 1);
        p1 += __shfl_xor_sync(0xffffffffu, p1, 2);
        if (tig == 0) {
            const int r = warpM * 64 + mt * 16 + gid;
            part_s[warpN * 128 + r]     = p0;
            part_s[warpN * 128 + r + 8] = p1;
        }
    }
    __syncthreads();
    if (tid < TM) {
        const float v = part_s[tid] + part_s[128 + tid];
        part[((size_t)z * 2 + blockIdx.x) * NB + blockIdx.y * TM + tid] = v;
    }
}

// ---------------------------------------------------------------------------
// Finalize: out[t,b] = sigmoid(part[t][0][b] + part[t][1][b] + bt2[t])
// ---------------------------------------------------------------------------
__global__ __launch_bounds__(256)
void finalize_kernel(const float* __restrict__ part, const float* __restrict__ bt2,
                     float* __restrict__ out)
{
    const int i = blockIdx.x * 256 + threadIdx.x;   // over NTASK*NB
    if (i >= NTASK * NB) return;
    const int t = i / NB;
    const int b = i - t * NB;
    const float v = part[((size_t)t * 2 + 0) * NB + b] +
                    part[((size_t)t * 2 + 1) * NB + b] + bt2[t];
    out[i] = 1.f / (1.f + expf(-v));
}

// ---------------------------------------------------------------------------
// Combine: tin[t,b,h] = sum_e gates[t,b,e] * eo[e,b,h]  (bf16 in/out)
// ---------------------------------------------------------------------------
__global__ __launch_bounds__(256)
void combine_kernel(const __nv_bfloat16* __restrict__ eo, const float* __restrict__ gates,
                    __nv_bfloat16* __restrict__ tin)
{
    const int idx = blockIdx.x * 256 + threadIdx.x;
    const int h8 = idx & (NH / 8 - 1);
    const int b  = idx >> 6;
    if (b >= NB) return;

    float g[NTASK][NE];
#pragma unroll
    for (int t = 0; t < NTASK; t++) {
        const float* gp = gates + ((size_t)t * NB + b) * NE;
#pragma unroll
        for (int e = 0; e < NE; e++) g[t][e] = gp[e];
    }

    float o[NTASK][8];
#pragma unroll
    for (int t = 0; t < NTASK; t++)
#pragma unroll
        for (int j = 0; j < 8; j++) o[t][j] = 0.f;

#pragma unroll
    for (int e = 0; e < NE; e++) {
        const __nv_bfloat162* v =
            (const __nv_bfloat162*)(eo + ((size_t)e * NB + b) * NH + h8 * 8);
        float2 f[4];
#pragma unroll
        for (int j = 0; j < 4; j++) f[j] = __bfloat1622float2(v[j]);
#pragma unroll
        for (int t = 0; t < NTASK; t++) {
            const float ge = g[t][e];
#pragma unroll
            for (int j = 0; j < 4; j++) {
                o[t][j * 2 + 0] = fmaf(ge, f[j].x, o[t][j * 2 + 0]);
                o[t][j * 2 + 1] = fmaf(ge, f[j].y, o[t][j * 2 + 1]);
            }
        }
    }
#pragma unroll
    for (int t = 0; t < NTASK; t++) {
        __nv_bfloat162* op = (__nv_bfloat162*)(tin + ((size_t)t * NB + b) * NH + h8 * 8);
#pragma unroll
        for (int j = 0; j < 4; j++)
            op[j] = __floats2bfloat162_rn(o[t][j * 2], o[t][j * 2 + 1]);
    }
}

// ---------------------------------------------------------------------------
// Launch — gates forked onto a second capture stream, joined before combine.
// ---------------------------------------------------------------------------
extern "C" void kernel_launch(void* const* d_in, const int* in_sizes, int n_in,
                              void* d_out, int out_size)
{
    const float* x   = (const float*)d_in[0];
    const float* We1 = (const float*)d_in[1];
    const float* be1 = (const float*)d_in[2];
    const float* We2 = (const float*)d_in[3];
    const float* be2 = (const float*)d_in[4];
    const float* Wg  = (const float*)d_in[5];
    const float* bg  = (const float*)d_in[6];
    const float* Wt1 = (const float*)d_in[7];
    const float* bt1 = (const float*)d_in[8];
    const float* Wt2 = (const float*)d_in[9];
    const float* bt2 = (const float*)d_in[10];
    float* out = (float*)d_out;

    __nv_bfloat16 *xb, *h1b, *eob, *tinb, *We1T, *We2T, *Wt1T;
    float *gates, *part;
    cudaGetSymbolAddress((void**)&xb,    g_xb);
    cudaGetSymbolAddress((void**)&h1b,   g_h1b);
    cudaGetSymbolAddress((void**)&eob,   g_eob);
    cudaGetSymbolAddress((void**)&tinb,  g_tinb);
    cudaGetSymbolAddress((void**)&gates, g_gates);
    cudaGetSymbolAddress((void**)&part,  g_part);
    cudaGetSymbolAddress((void**)&We1T,  g_We1T);
    cudaGetSymbolAddress((void**)&We2T,  g_We2T);
    cudaGetSymbolAddress((void**)&Wt1T,  g_Wt1T);

    cudaFuncSetAttribute(gemm_bf16_kernel,
                         cudaFuncAttributeMaxDynamicSharedMemorySize, SMEM_BYTES);
    cudaFuncSetAttribute(tower_gemm_kernel,
                         cudaFuncAttributeMaxDynamicSharedMemorySize, TW_SMEM);
    cudaFuncSetAttribute(gates_kernel,
                         cudaFuncAttributeMaxDynamicSharedMemorySize, GATES_SMEM);

    // Fork a side stream for the gates path (graph-capture-legal pattern).
    cudaStream_t s2;
    cudaEvent_t ev_fork, ev_gates;
    cudaStreamCreateWithFlags(&s2, cudaStreamNonBlocking);
    cudaEventCreateWithFlags(&ev_fork, cudaEventDisableTiming);
    cudaEventCreateWithFlags(&ev_gates, cudaEventDisableTiming);

    cudaEventRecord(ev_fork, 0);
    cudaStreamWaitEvent(s2, ev_fork, 0);

    // Side stream: gate logits + softmax (only needed by combine)
    gates_kernel<<<NB / 32, 256, GATES_SMEM, s2>>>(x, Wg, bg, gates);
    cudaEventRecord(ev_gates, s2);

    // Main stream: merged prep (weight transposes + x convert), one launch
    prep_all_kernel<<<6528 + 16384, 256>>>(We1, We1T, We2, We2T, Wt1, Wt1T, x, xb);

    // Expert layer 1: h1[e] = relu(x @ We1[e] + be1[e])  (2 M-tiles per CTA)
    gemm_bf16_kernel<<<dim3(NH / TN, NB / (TM * MTILES), NE), 128, SMEM_BYTES>>>(
        xb, We1T, be1, h1b, ND, NH,
        0LL, (long long)NH * ND, (long long)NH, (long long)NB * NH);

    // Expert layer 2: eo[e] = relu(h1[e] @ We2[e] + be2[e])
    gemm_bf16_kernel<<<dim3(NH / TN, NB / (TM * MTILES), NE), 128, SMEM_BYTES>>>(
        h1b, We2T, be2, eob, NH, NH,
        (long long)NB * NH, (long long)NH * NH, (long long)NH, (long long)NB * NH);

    // Join gates before combine
    cudaStreamWaitEvent(0, ev_gates, 0);
    combine_kernel<<<(NB * (NH / 8)) / 256, 256>>>(eob, gates, tinb);

    // Tower GEMM with fused head partials, then finalize (sigmoid)
    tower_gemm_kernel<<<dim3(NT / TN, NB / TM, NTASK), 128, TW_SMEM>>>(
        tinb, Wt1T, bt1, Wt2, part);
    finalize_kernel<<<(NTASK * NB + 255) / 256, 256>>>(part, bt2, out);
}

// round 14
// speedup vs baseline: 1.0623x; 1.0623x over previous
#include <cuda_runtime.h>
#include <cuda_bf16.h>
#include <math.h>
#include <stdint.h>

// Problem constants
#define NB 16384
#define ND 1024
#define NE 8
#define NH 512
#define NT 256
#define NTASK 3

// GEMM tiling (bf16 mma.sync m16n8k16)
#define TM 128
#define TN 128
#define BK 64
#define NSTAGE 3
#define STAGE_BYTES 16384             // 128 rows x 128 B (64 bf16)
#define OFF_B (NSTAGE * STAGE_BYTES)  // 49152
#define OFF_BIAS (2 * NSTAGE * STAGE_BYTES)   // 98304
#define SMEM_BYTES (OFF_BIAS + 512)   // 98816 -> 2 CTAs/SM

// Tower kernel extra smem (on top of the GEMM layout)
#define TW_OFF_W2   (OFF_BIAS + 512)          // 128 floats
#define TW_OFF_PART (TW_OFF_W2 + 512)         // 2 x 128 floats
#define TW_SMEM     (TW_OFF_PART + 1024)      // 100352 -> still 2 CTAs/SM

// Gates kernel smem: 24 rows x 1032 floats
#define WG_PITCH 1032
#define GATES_SMEM (NTASK * NE * WG_PITCH * 4)

// ---------------------------------------------------------------------------
// Scratch (device globals; no runtime allocation allowed)
// ---------------------------------------------------------------------------
__device__ __nv_bfloat16 g_xb[(size_t)NB * ND];            // x in bf16
__device__ __nv_bfloat16 g_h1b[(size_t)NE * NB * NH];      // [E,B,H] bf16
__device__ __nv_bfloat16 g_eob[(size_t)NE * NB * NH];      // [E,B,H] bf16
__device__ __nv_bfloat16 g_tinb[(size_t)NTASK * NB * NH];  // [T,B,H] bf16
__device__ float g_gates[(size_t)NTASK * NB * NE];         // [T,B,E]
__device__ float g_part[(size_t)NTASK * 2 * NB];           // tower head partials
__device__ __nv_bfloat16 g_We1T[(size_t)NE * NH * ND];     // [E,H,D] bf16 NK
__device__ __nv_bfloat16 g_We2T[(size_t)NE * NH * NH];     // [E,H,H]
__device__ __nv_bfloat16 g_Wt1T[(size_t)NTASK * NT * NH];  // [T,NT,H]

// ---------------------------------------------------------------------------
// Helpers (sm_80-class PTX only)
// ---------------------------------------------------------------------------
__device__ __forceinline__ uint32_t smem_u32(const void* p) {
    uint32_t a;
    asm("{ .reg .u64 t; cvta.to.shared.u64 t, %1; cvt.u32.u64 %0, t; }" : "=r"(a) : "l"(p));
    return a;
}

#define CP_ASYNC16(dst, src) \
    asm volatile("cp.async.cg.shared.global [%0], [%1], 16;" :: "r"(dst), "l"(src))
#define CP_COMMIT() asm volatile("cp.async.commit_group;" ::: "memory")
#define CP_WAIT1()  asm volatile("cp.async.wait_group 1;" ::: "memory")
#define CP_WAIT0()  asm volatile("cp.async.wait_group 0;" ::: "memory")

__device__ __forceinline__ void ldmatrix_x4(uint32_t& r0, uint32_t& r1,
                                            uint32_t& r2, uint32_t& r3, uint32_t addr) {
    asm volatile("ldmatrix.sync.aligned.m8n8.x4.shared.b16 {%0,%1,%2,%3}, [%4];"
                 : "=r"(r0), "=r"(r1), "=r"(r2), "=r"(r3) : "r"(addr));
}

__device__ __forceinline__ void mma_bf16(float (&d)[4], const uint32_t (&a)[4],
                                         const uint32_t (&b)[2]) {
    asm volatile(
        "mma.sync.aligned.m16n8k16.row.col.f32.bf16.bf16.f32 "
        "{%0,%1,%2,%3}, {%4,%5,%6,%7}, {%8,%9}, {%0,%1,%2,%3};"
        : "+f"(d[0]), "+f"(d[1]), "+f"(d[2]), "+f"(d[3])
        : "r"(a[0]), "r"(a[1]), "r"(a[2]), "r"(a[3]), "r"(b[0]), "r"(b[1]));
}

__device__ __forceinline__ uint32_t sw128(uint32_t off) {
    return off ^ ((off >> 3) & 0x70);
}

// ---------------------------------------------------------------------------
// Merged prep: weight transposes (bf16) + x fp32->bf16 convert, one launch.
// bid < 6528: transpose tiles; bid >= 6528: f2b blocks.
// ---------------------------------------------------------------------------
__global__ __launch_bounds__(256)
void prep_all_kernel(const float* __restrict__ We1, __nv_bfloat16* __restrict__ We1T,
                     const float* __restrict__ We2, __nv_bfloat16* __restrict__ We2T,
                     const float* __restrict__ Wt1, __nv_bfloat16* __restrict__ Wt1T,
                     const float* __restrict__ x,   __nv_bfloat16* __restrict__ xb)
{
    const int bid = blockIdx.x;
    if (bid >= 6528) {
        // f2b: 16384 blocks x 256 threads x 1 float4
        const int i = (bid - 6528) * 256 + threadIdx.x;
        float4 v = ((const float4*)x)[i];
        __nv_bfloat162* o = (__nv_bfloat162*)xb + (size_t)i * 2;
        o[0] = __floats2bfloat162_rn(v.x, v.y);
        o[1] = __floats2bfloat162_rn(v.z, v.w);
        return;
    }

    __shared__ float t[32][33];
    const float* in;
    __nv_bfloat16* out;
    int K, N, z, ky, nx;
    if (bid < 4096) {                    // We1: z=8, K=1024, N=512
        const int r = bid;
        z = r >> 9; const int tt = r & 511;
        ky = tt >> 4; nx = tt & 15;
        K = ND; N = NH; in = We1; out = We1T;
    } else if (bid < 6144) {             // We2: z=8, K=512, N=512
        const int r = bid - 4096;
        z = r >> 8; const int tt = r & 255;
        ky = tt >> 4; nx = tt & 15;
        K = NH; N = NH; in = We2; out = We2T;
    } else {                             // Wt1: z=3, K=512, N=256
        const int r = bid - 6144;
        z = r >> 7; const int tt = r & 127;
        ky = tt >> 3; nx = tt & 7;
        K = NH; N = NT; in = Wt1; out = Wt1T;
    }
    in  += (size_t)z * K * N;
    out += (size_t)z * K * N;
    const int k0 = ky * 32, n0 = nx * 32;
    const int tx = threadIdx.x & 31, ty = threadIdx.x >> 5;
#pragma unroll
    for (int i = 0; i < 32; i += 8)
        t[ty + i][tx] = in[(size_t)(k0 + ty + i) * N + n0 + tx];
    __syncthreads();
#pragma unroll
    for (int i = 0; i < 32; i += 8)
        out[(size_t)(n0 + ty + i) * K + k0 + tx] = __float2bfloat16_rn(t[tx][ty + i]);
}

// ---------------------------------------------------------------------------
// Gates kernel (forked stream): x.Wg + softmax, 4 rows per thread.
// ---------------------------------------------------------------------------
__global__ __launch_bounds__(256)
void gates_kernel(const float* __restrict__ x, const float* __restrict__ Wg,
                  const float* __restrict__ bg, float* __restrict__ gates)
{
    extern __shared__ float wg_s[];   // [24][WG_PITCH]
    const int tid = threadIdx.x;

    for (int i = tid; i < NTASK * ND * NE / 4; i += 256) {
        const float4 v = ((const float4*)Wg)[i];
        const int base = i * 4;
        const int tt = base / (ND * NE);
        const int r  = base - tt * (ND * NE);
        const int d  = r >> 3;
        const int e0 = r & 7;
        wg_s[(tt * NE + e0 + 0) * WG_PITCH + d] = v.x;
        wg_s[(tt * NE + e0 + 1) * WG_PITCH + d] = v.y;
        wg_s[(tt * NE + e0 + 2) * WG_PITCH + d] = v.z;
        wg_s[(tt * NE + e0 + 3) * WG_PITCH + d] = v.w;
    }
    __syncthreads();

    const int wid = tid >> 5, lane = tid & 31;
    const int b0 = blockIdx.x * 32 + wid * 4;

    const float4* xr0 = (const float4*)(x + (size_t)(b0 + 0) * ND);
    const float4* xr1 = (const float4*)(x + (size_t)(b0 + 1) * ND);
    const float4* xr2 = (const float4*)(x + (size_t)(b0 + 2) * ND);
    const float4* xr3 = (const float4*)(x + (size_t)(b0 + 3) * ND);

    float acc[4][24];
#pragma unroll
    for (int r = 0; r < 4; r++)
#pragma unroll
        for (int te = 0; te < 24; te++) acc[r][te] = 0.f;

#pragma unroll
    for (int i = 0; i < 8; i++) {
        const int d4 = lane + 32 * i;
        float4 xv[4];
        xv[0] = xr0[d4]; xv[1] = xr1[d4]; xv[2] = xr2[d4]; xv[3] = xr3[d4];
#pragma unroll
        for (int te = 0; te < 24; te++) {
            const float4 wv = *(const float4*)(wg_s + te * WG_PITCH + d4 * 4);
#pragma unroll
            for (int r = 0; r < 4; r++) {
                acc[r][te] += xv[r].x * wv.x + xv[r].y * wv.y +
                              xv[r].z * wv.z + xv[r].w * wv.w;
            }
        }
    }
#pragma unroll
    for (int off = 16; off > 0; off >>= 1)
#pragma unroll
        for (int r = 0; r < 4; r++)
#pragma unroll
            for (int te = 0; te < 24; te++)
                acc[r][te] += __shfl_xor_sync(0xffffffffu, acc[r][te], off);

    if (lane < NTASK) {
        const int t = lane;
#pragma unroll
        for (int r = 0; r < 4; r++) {
            float v[NE];
            float mx = -1e30f;
#pragma unroll
            for (int e = 0; e < NE; e++) {
                v[e] = acc[r][t * NE + e] + bg[t * NE + e];
                mx = fmaxf(mx, v[e]);
            }
            float s = 0.f;
#pragma unroll
            for (int e = 0; e < NE; e++) { v[e] = expf(v[e] - mx); s += v[e]; }
            const float inv = 1.f / s;
            float* gout = gates + ((size_t)t * NB + b0 + r) * NE;
#pragma unroll
            for (int e = 0; e < NE; e++) gout[e] = v[e] * inv;
        }
    }
}

// ---------------------------------------------------------------------------
// bf16 tensor-core batched GEMM (expert layers): C = relu(A @ Bt^T + bias)
// CTA tile 128x128, BK=64, 3-stage cp.async, 4 warps, 64x64 warp tiles.
// (Exact R12 structure — best measured configuration.)
// ---------------------------------------------------------------------------
__global__ __launch_bounds__(128, 2)
void gemm_bf16_kernel(const __nv_bfloat16* __restrict__ Ab,
                      const __nv_bfloat16* __restrict__ Bb,
                      const float* __restrict__ biasb, __nv_bfloat16* __restrict__ Cb,
                      int K, int ldc,
                      long long sA, long long sB, long long sBias, long long sC)
{
    extern __shared__ char dynsmem[];
    const uint32_t smb = smem_u32(dynsmem);

    const int z = blockIdx.z;
    const __nv_bfloat16* A  = Ab + (size_t)z * sA + (size_t)(blockIdx.y * TM) * K;
    const __nv_bfloat16* Bt = Bb + (size_t)z * sB + (size_t)(blockIdx.x * TN) * K;
    const float* bias = biasb + (size_t)z * sBias + blockIdx.x * TN;
    __nv_bfloat16* C = Cb + (size_t)z * sC + (size_t)(blockIdx.y * TM) * ldc + blockIdx.x * TN;

    const int tid   = threadIdx.x;
    const int wid   = tid >> 5;
    const int lane  = tid & 31;
    const int gid   = lane >> 2;
    const int tig   = lane & 3;
    const int warpM = wid >> 1;
    const int warpN = wid & 1;

    float* bias_s = (float*)(dynsmem + OFF_BIAS);
    if (tid < TN) bias_s[tid] = bias[tid];

    auto load_stage = [&](int buf, int k0) {
        const __nv_bfloat16* Ag = A + k0;
        const __nv_bfloat16* Bg = Bt + k0;
#pragma unroll
        for (int i = 0; i < 8; i++) {
            const int idx = tid + i * 128;
            const int row = idx >> 3;
            const int c8  = idx & 7;
            const uint32_t off = sw128((uint32_t)(row * 128 + c8 * 16));
            CP_ASYNC16(smb + buf * STAGE_BYTES + off, Ag + (size_t)row * K + c8 * 8);
            CP_ASYNC16(smb + OFF_B + buf * STAGE_BYTES + off, Bg + (size_t)row * K + c8 * 8);
        }
        CP_COMMIT();
    };

    float acc[4][8][4];
#pragma unroll
    for (int mt = 0; mt < 4; mt++)
#pragma unroll
        for (int nt = 0; nt < 8; nt++)
#pragma unroll
            for (int r = 0; r < 4; r++) acc[mt][nt][r] = 0.f;

    const int a_row  = warpM * 64 + (lane & 15);
    const int a_koff = (lane >> 4) * 16;
    const int b_row  = warpN * 64 + (lane & 7) + ((lane >> 4) << 3);
    const int b_koff = ((lane >> 3) & 1) * 16;

    uint32_t af[2][4][4];
    uint32_t bf[2][8][2];

    const int ns = K / BK;
    load_stage(0, 0);
    load_stage(1, BK);

    for (int s = 0; s < ns; s++) {
        if (s + 1 < ns) CP_WAIT1(); else CP_WAIT0();
        __syncthreads();   // single barrier per stage (fences (s+2)%3 reuse too)

        const int buf = s % NSTAGE;
        const uint32_t sa = smb + buf * STAGE_BYTES;
        const uint32_t sb = smb + OFF_B + buf * STAGE_BYTES;

        // fragments for kk=0
#pragma unroll
        for (int mt = 0; mt < 4; mt++) {
            const uint32_t off = (uint32_t)((a_row + mt * 16) * 128 + a_koff);
            ldmatrix_x4(af[0][mt][0], af[0][mt][1], af[0][mt][2], af[0][mt][3],
                        sa + sw128(off));
        }
#pragma unroll
        for (int pr = 0; pr < 4; pr++) {
            const uint32_t off = (uint32_t)((b_row + pr * 16) * 128 + b_koff);
            ldmatrix_x4(bf[0][pr * 2][0], bf[0][pr * 2][1],
                        bf[0][pr * 2 + 1][0], bf[0][pr * 2 + 1][1], sb + sw128(off));
        }

#pragma unroll
        for (int kk = 0; kk < 4; kk++) {
            const int cur = kk & 1;
            const int nxt = cur ^ 1;
            if (kk < 3) {
#pragma unroll
                for (int mt = 0; mt < 4; mt++) {
                    const uint32_t off =
                        (uint32_t)((a_row + mt * 16) * 128 + (kk + 1) * 32 + a_koff);
                    ldmatrix_x4(af[nxt][mt][0], af[nxt][mt][1], af[nxt][mt][2],
                                af[nxt][mt][3], sa + sw128(off));
                }
#pragma unroll
                for (int pr = 0; pr < 4; pr++) {
                    const uint32_t off =
                        (uint32_t)((b_row + pr * 16) * 128 + (kk + 1) * 32 + b_koff);
                    ldmatrix_x4(bf[nxt][pr * 2][0], bf[nxt][pr * 2][1],
                                bf[nxt][pr * 2 + 1][0], bf[nxt][pr * 2 + 1][1],
                                sb + sw128(off));
                }
            }
#pragma unroll
            for (int mt = 0; mt < 4; mt++)
#pragma unroll
                for (int nt = 0; nt < 8; nt++)
                    mma_bf16(acc[mt][nt], af[cur][mt], bf[cur][nt]);
        }
        if (s + 2 < ns) load_stage((s + 2) % NSTAGE, (s + 2) * BK);
    }

    // Epilogue: bias + relu -> bf16
#pragma unroll
    for (int mt = 0; mt < 4; mt++) {
        const int r0 = warpM * 64 + mt * 16 + gid;
#pragma unroll
        for (int nt = 0; nt < 8; nt++) {
            const int c = warpN * 64 + nt * 8 + tig * 2;
            const float2 bv = *(const float2*)(bias_s + c);
            float v0 = fmaxf(acc[mt][nt][0] + bv.x, 0.f);
            float v1 = fmaxf(acc[mt][nt][1] + bv.y, 0.f);
            float v2 = fmaxf(acc[mt][nt][2] + bv.x, 0.f);
            float v3 = fmaxf(acc[mt][nt][3] + bv.y, 0.f);
            *(__nv_bfloat162*)(C + (size_t)r0 * ldc + c) = __floats2bfloat162_rn(v0, v1);
            *(__nv_bfloat162*)(C + (size_t)(r0 + 8) * ldc + c) = __floats2bfloat162_rn(v2, v3);
        }
    }
}

// ---------------------------------------------------------------------------
// Tower GEMM with fused head-partial epilogue. grid = (2, NB/128, NTASK).
// ---------------------------------------------------------------------------
__global__ __launch_bounds__(128, 2)
void tower_gemm_kernel(const __nv_bfloat16* __restrict__ tin,
                       const __nv_bfloat16* __restrict__ Wt1T,
                       const float* __restrict__ bt1,
                       const float* __restrict__ Wt2,
                       float* __restrict__ part)
{
    extern __shared__ char dynsmem[];
    const uint32_t smb = smem_u32(dynsmem);
    const int K = NH;

    const int z = blockIdx.z;
    const __nv_bfloat16* A  = tin + (size_t)z * NB * NH + (size_t)(blockIdx.y * TM) * K;
    const __nv_bfloat16* Bt = Wt1T + (size_t)z * NT * NH + (size_t)(blockIdx.x * TN) * K;

    const int tid   = threadIdx.x;
    const int wid   = tid >> 5;
    const int lane  = tid & 31;
    const int gid   = lane >> 2;
    const int tig   = lane & 3;
    const int warpM = wid >> 1;
    const int warpN = wid & 1;

    float* bias_s = (float*)(dynsmem + OFF_BIAS);
    float* w2_s   = (float*)(dynsmem + TW_OFF_W2);
    float* part_s = (float*)(dynsmem + TW_OFF_PART);  // [2][128]
    if (tid < TN) {
        bias_s[tid] = bt1[z * NT + blockIdx.x * TN + tid];
        w2_s[tid]   = Wt2[z * NT + blockIdx.x * TN + tid];
    }

    auto load_stage = [&](int buf, int k0) {
        const __nv_bfloat16* Ag = A + k0;
        const __nv_bfloat16* Bg = Bt + k0;
#pragma unroll
        for (int i = 0; i < 8; i++) {
            const int idx = tid + i * 128;
            const int row = idx >> 3;
            const int c8  = idx & 7;
            const uint32_t off = sw128((uint32_t)(row * 128 + c8 * 16));
            CP_ASYNC16(smb + buf * STAGE_BYTES + off, Ag + (size_t)row * K + c8 * 8);
            CP_ASYNC16(smb + OFF_B + buf * STAGE_BYTES + off, Bg + (size_t)row * K + c8 * 8);
        }
        CP_COMMIT();
    };

    float acc[4][8][4];
#pragma unroll
    for (int mt = 0; mt < 4; mt++)
#pragma unroll
        for (int nt = 0; nt < 8; nt++)
#pragma unroll
            for (int r = 0; r < 4; r++) acc[mt][nt][r] = 0.f;

    const int a_row  = warpM * 64 + (lane & 15);
    const int a_koff = (lane >> 4) * 16;
    const int b_row  = warpN * 64 + (lane & 7) + ((lane >> 4) << 3);
    const int b_koff = ((lane >> 3) & 1) * 16;

    uint32_t af[2][4][4];
    uint32_t bf[2][8][2];

    const int ns = K / BK;      // 8
    load_stage(0, 0);
    load_stage(1, BK);

    for (int s = 0; s < ns; s++) {
        if (s + 1 < ns) CP_WAIT1(); else CP_WAIT0();
        __syncthreads();

        const int buf = s % NSTAGE;
        const uint32_t sa = smb + buf * STAGE_BYTES;
        const uint32_t sb = smb + OFF_B + buf * STAGE_BYTES;

#pragma unroll
        for (int mt = 0; mt < 4; mt++) {
            const uint32_t off = (uint32_t)((a_row + mt * 16) * 128 + a_koff);
            ldmatrix_x4(af[0][mt][0], af[0][mt][1], af[0][mt][2], af[0][mt][3],
                        sa + sw128(off));
        }
#pragma unroll
        for (int pr = 0; pr < 4; pr++) {
            const uint32_t off = (uint32_t)((b_row + pr * 16) * 128 + b_koff);
            ldmatrix_x4(bf[0][pr * 2][0], bf[0][pr * 2][1],
                        bf[0][pr * 2 + 1][0], bf[0][pr * 2 + 1][1], sb + sw128(off));
        }

#pragma unroll
        for (int kk = 0; kk < 4; kk++) {
            const int cur = kk & 1;
            const int nxt = cur ^ 1;
            if (kk < 3) {
#pragma unroll
                for (int mt = 0; mt < 4; mt++) {
                    const uint32_t off =
                        (uint32_t)((a_row + mt * 16) * 128 + (kk + 1) * 32 + a_koff);
                    ldmatrix_x4(af[nxt][mt][0], af[nxt][mt][1], af[nxt][mt][2],
                                af[nxt][mt][3], sa + sw128(off));
                }
#pragma unroll
                for (int pr = 0; pr < 4; pr++) {
                    const uint32_t off =
                        (uint32_t)((b_row + pr * 16) * 128 + (kk + 1) * 32 + b_koff);
                    ldmatrix_x4(bf[nxt][pr * 2][0], bf[nxt][pr * 2][1],
                                bf[nxt][pr * 2 + 1][0], bf[nxt][pr * 2 + 1][1],
                                sb + sw128(off));
                }
            }
#pragma unroll
            for (int mt = 0; mt < 4; mt++)
#pragma unroll
                for (int nt = 0; nt < 8; nt++)
                    mma_bf16(acc[mt][nt], af[cur][mt], bf[cur][nt]);
        }
        if (s + 2 < ns) load_stage((s + 2) % NSTAGE, (s + 2) * BK);
    }

    // Fused head-partial epilogue.
#pragma unroll
    for (int mt = 0; mt < 4; mt++) {
        float p0 = 0.f, p1 = 0.f;
#pragma unroll
        for (int nt = 0; nt < 8; nt++) {
            const int c = warpN * 64 + nt * 8 + tig * 2;
            const float b0 = bias_s[c], b1 = bias_s[c + 1];
            const float w0 = w2_s[c],  w1 = w2_s[c + 1];
            p0 += fmaxf(acc[mt][nt][0] + b0, 0.f) * w0 + fmaxf(acc[mt][nt][1] + b1, 0.f) * w1;
            p1 += fmaxf(acc[mt][nt][2] + b0, 0.f) * w0 + fmaxf(acc[mt][nt][3] + b1, 0.f) * w1;
        }
        p0 += __shfl_xor_sync(0xffffffffu, p0, 1);
        p0 += __shfl_xor_sync(0xffffffffu, p0, 2);
        p1 += __shfl_xor_sync(0xffffffffu, p1, 1);
        p1 += __shfl_xor_sync(0xffffffffu, p1, 2);
        if (tig == 0) {
            const int r = warpM * 64 + mt * 16 + gid;
            part_s[warpN * 128 + r]     = p0;
            part_s[warpN * 128 + r + 8] = p1;
        }
    }
    __syncthreads();
    if (tid < TM) {
        const float v = part_s[tid] + part_s[128 + tid];
        part[((size_t)z * 2 + blockIdx.x) * NB + blockIdx.y * TM + tid] = v;
    }
}

// ---------------------------------------------------------------------------
// Finalize: out[t,b] = sigmoid(part[t][0][b] + part[t][1][b] + bt2[t])
// ---------------------------------------------------------------------------
__global__ __launch_bounds__(256)
void finalize_kernel(const float* __restrict__ part, const float* __restrict__ bt2,
                     float* __restrict__ out)
{
    const int i = blockIdx.x * 256 + threadIdx.x;   // over NTASK*NB
    if (i >= NTASK * NB) return;
    const int t = i / NB;
    const int b = i - t * NB;
    const float v = part[((size_t)t * 2 + 0) * NB + b] +
                    part[((size_t)t * 2 + 1) * NB + b] + bt2[t];
    out[i] = 1.f / (1.f + expf(-v));
}

// ---------------------------------------------------------------------------
// Combine: tin[t,b,h] = sum_e gates[t,b,e] * eo[e,b,h]  (bf16 in/out)
// ---------------------------------------------------------------------------
__global__ __launch_bounds__(256)
void combine_kernel(const __nv_bfloat16* __restrict__ eo, const float* __restrict__ gates,
                    __nv_bfloat16* __restrict__ tin)
{
    const int idx = blockIdx.x * 256 + threadIdx.x;
    const int h8 = idx & (NH / 8 - 1);
    const int b  = idx >> 6;
    if (b >= NB) return;

    float g[NTASK][NE];
#pragma unroll
    for (int t = 0; t < NTASK; t++) {
        const float* gp = gates + ((size_t)t * NB + b) * NE;
#pragma unroll
        for (int e = 0; e < NE; e++) g[t][e] = gp[e];
    }

    float o[NTASK][8];
#pragma unroll
    for (int t = 0; t < NTASK; t++)
#pragma unroll
        for (int j = 0; j < 8; j++) o[t][j] = 0.f;

#pragma unroll
    for (int e = 0; e < NE; e++) {
        const __nv_bfloat162* v =
            (const __nv_bfloat162*)(eo + ((size_t)e * NB + b) * NH + h8 * 8);
        float2 f[4];
#pragma unroll
        for (int j = 0; j < 4; j++) f[j] = __bfloat1622float2(v[j]);
#pragma unroll
        for (int t = 0; t < NTASK; t++) {
            const float ge = g[t][e];
#pragma unroll
            for (int j = 0; j < 4; j++) {
                o[t][j * 2 + 0] = fmaf(ge, f[j].x, o[t][j * 2 + 0]);
                o[t][j * 2 + 1] = fmaf(ge, f[j].y, o[t][j * 2 + 1]);
            }
        }
    }
#pragma unroll
    for (int t = 0; t < NTASK; t++) {
        __nv_bfloat162* op = (__nv_bfloat162*)(tin + ((size_t)t * NB + b) * NH + h8 * 8);
#pragma unroll
        for (int j = 0; j < 4; j++)
            op[j] = __floats2bfloat162_rn(o[t][j * 2], o[t][j * 2 + 1]);
    }
}

// ---------------------------------------------------------------------------
// Launch — gates forked onto a second capture stream, joined before combine.
// ---------------------------------------------------------------------------
extern "C" void kernel_launch(void* const* d_in, const int* in_sizes, int n_in,
                              void* d_out, int out_size)
{
    const float* x   = (const float*)d_in[0];
    const float* We1 = (const float*)d_in[1];
    const float* be1 = (const float*)d_in[2];
    const float* We2 = (const float*)d_in[3];
    const float* be2 = (const float*)d_in[4];
    const float* Wg  = (const float*)d_in[5];
    const float* bg  = (const float*)d_in[6];
    const float* Wt1 = (const float*)d_in[7];
    const float* bt1 = (const float*)d_in[8];
    const float* Wt2 = (const float*)d_in[9];
    const float* bt2 = (const float*)d_in[10];
    float* out = (float*)d_out;

    __nv_bfloat16 *xb, *h1b, *eob, *tinb, *We1T, *We2T, *Wt1T;
    float *gates, *part;
    cudaGetSymbolAddress((void**)&xb,    g_xb);
    cudaGetSymbolAddress((void**)&h1b,   g_h1b);
    cudaGetSymbolAddress((void**)&eob,   g_eob);
    cudaGetSymbolAddress((void**)&tinb,  g_tinb);
    cudaGetSymbolAddress((void**)&gates, g_gates);
    cudaGetSymbolAddress((void**)&part,  g_part);
    cudaGetSymbolAddress((void**)&We1T,  g_We1T);
    cudaGetSymbolAddress((void**)&We2T,  g_We2T);
    cudaGetSymbolAddress((void**)&Wt1T,  g_Wt1T);

    cudaFuncSetAttribute(gemm_bf16_kernel,
                         cudaFuncAttributeMaxDynamicSharedMemorySize, SMEM_BYTES);
    cudaFuncSetAttribute(tower_gemm_kernel,
                         cudaFuncAttributeMaxDynamicSharedMemorySize, TW_SMEM);
    cudaFuncSetAttribute(gates_kernel,
                         cudaFuncAttributeMaxDynamicSharedMemorySize, GATES_SMEM);

    // Fork a side stream for the gates path (graph-capture-legal pattern).
    cudaStream_t s2;
    cudaEvent_t ev_fork, ev_gates;
    cudaStreamCreateWithFlags(&s2, cudaStreamNonBlocking);
    cudaEventCreateWithFlags(&ev_fork, cudaEventDisableTiming);
    cudaEventCreateWithFlags(&ev_gates, cudaEventDisableTiming);

    cudaEventRecord(ev_fork, 0);
    cudaStreamWaitEvent(s2, ev_fork, 0);

    // Side stream: gate logits + softmax (only needed by combine)
    gates_kernel<<<NB / 32, 256, GATES_SMEM, s2>>>(x, Wg, bg, gates);
    cudaEventRecord(ev_gates, s2);

    // Main stream: merged prep (weight transposes + x convert), one launch
    prep_all_kernel<<<6528 + 16384, 256>>>(We1, We1T, We2, We2T, Wt1, Wt1T, x, xb);

    // Expert layer 1: h1[e] = relu(x @ We1[e] + be1[e])
    gemm_bf16_kernel<<<dim3(NH / TN, NB / TM, NE), 128, SMEM_BYTES>>>(
        xb, We1T, be1, h1b, ND, NH,
        0LL, (long long)NH * ND, (long long)NH, (long long)NB * NH);

    // Expert layer 2: eo[e] = relu(h1[e] @ We2[e] + be2[e])
    gemm_bf16_kernel<<<dim3(NH / TN, NB / TM, NE), 128, SMEM_BYTES>>>(
        h1b, We2T, be2, eob, NH, NH,
        (long long)NB * NH, (long long)NH * NH, (long long)NH, (long long)NB * NH);

    // Join gates before combine
    cudaStreamWaitEvent(0, ev_gates, 0);
    combine_kernel<<<(NB * (NH / 8)) / 256, 256>>>(eob, gates, tinb);

    // Tower GEMM with fused head partials, then finalize (sigmoid)
    tower_gemm_kernel<<<dim3(NT / TN, NB / TM, NTASK), 128, TW_SMEM>>>(
        tinb, Wt1T, bt1, Wt2, part);
    finalize_kernel<<<(NTASK * NB + 255) / 256, 256>>>(part, bt2, out);
}

// round 15
// speedup vs baseline: 1.0637x; 1.0013x over previous
#include <cuda_runtime.h>
#include <cuda_bf16.h>
#include <math.h>
#include <stdint.h>

// Problem constants
#define NB 16384
#define ND 1024
#define NE 8
#define NH 512
#define NT 256
#define NTASK 3
#define NBH (NB / 2)                  // batch half

// GEMM tiling (bf16 mma.sync m16n8k16)
#define TM 128
#define TN 128
#define BK 64
#define NSTAGE 3
#define STAGE_BYTES 16384             // 128 rows x 128 B (64 bf16)
#define OFF_B (NSTAGE * STAGE_BYTES)  // 49152
#define OFF_BIAS (2 * NSTAGE * STAGE_BYTES)   // 98304
#define SMEM_BYTES (OFF_BIAS + 512)   // 98816 -> 2 CTAs/SM

// Tower kernel extra smem (on top of the GEMM layout)
#define TW_OFF_W2   (OFF_BIAS + 512)          // 128 floats
#define TW_OFF_PART (TW_OFF_W2 + 512)         // 2 x 128 floats
#define TW_SMEM     (TW_OFF_PART + 1024)      // 100352 -> still 2 CTAs/SM

// Gates kernel smem: 24 rows x 1032 floats
#define WG_PITCH 1032
#define GATES_SMEM (NTASK * NE * WG_PITCH * 4)

// ---------------------------------------------------------------------------
// Scratch (device globals; no runtime allocation allowed)
// ---------------------------------------------------------------------------
__device__ __nv_bfloat16 g_xb[(size_t)NB * ND];            // x in bf16
__device__ __nv_bfloat16 g_h1b[(size_t)NE * NB * NH];      // [E,B,H] bf16
__device__ __nv_bfloat16 g_eob[(size_t)NE * NB * NH];      // [E,B,H] bf16
__device__ __nv_bfloat16 g_tinb[(size_t)NTASK * NB * NH];  // [T,B,H] bf16
__device__ float g_gates[(size_t)NTASK * NB * NE];         // [T,B,E]
__device__ float g_part[(size_t)NTASK * 2 * NB];           // tower head partials
__device__ __nv_bfloat16 g_We1T[(size_t)NE * NH * ND];     // [E,H,D] bf16 NK
__device__ __nv_bfloat16 g_We2T[(size_t)NE * NH * NH];     // [E,H,H]
__device__ __nv_bfloat16 g_Wt1T[(size_t)NTASK * NT * NH];  // [T,NT,H]

// ---------------------------------------------------------------------------
// Helpers (sm_80-class PTX only)
// ---------------------------------------------------------------------------
__device__ __forceinline__ uint32_t smem_u32(const void* p) {
    uint32_t a;
    asm("{ .reg .u64 t; cvta.to.shared.u64 t, %1; cvt.u32.u64 %0, t; }" : "=r"(a) : "l"(p));
    return a;
}

#define CP_ASYNC16(dst, src) \
    asm volatile("cp.async.cg.shared.global [%0], [%1], 16;" :: "r"(dst), "l"(src))
#define CP_COMMIT() asm volatile("cp.async.commit_group;" ::: "memory")
#define CP_WAIT1()  asm volatile("cp.async.wait_group 1;" ::: "memory")
#define CP_WAIT0()  asm volatile("cp.async.wait_group 0;" ::: "memory")

__device__ __forceinline__ void ldmatrix_x4(uint32_t& r0, uint32_t& r1,
                                            uint32_t& r2, uint32_t& r3, uint32_t addr) {
    asm volatile("ldmatrix.sync.aligned.m8n8.x4.shared.b16 {%0,%1,%2,%3}, [%4];"
                 : "=r"(r0), "=r"(r1), "=r"(r2), "=r"(r3) : "r"(addr));
}

__device__ __forceinline__ void mma_bf16(float (&d)[4], const uint32_t (&a)[4],
                                         const uint32_t (&b)[2]) {
    asm volatile(
        "mma.sync.aligned.m16n8k16.row.col.f32.bf16.bf16.f32 "
        "{%0,%1,%2,%3}, {%4,%5,%6,%7}, {%8,%9}, {%0,%1,%2,%3};"
        : "+f"(d[0]), "+f"(d[1]), "+f"(d[2]), "+f"(d[3])
        : "r"(a[0]), "r"(a[1]), "r"(a[2]), "r"(a[3]), "r"(b[0]), "r"(b[1]));
}

__device__ __forceinline__ uint32_t sw128(uint32_t off) {
    return off ^ ((off >> 3) & 0x70);
}

// ---------------------------------------------------------------------------
// Merged prep: weight transposes (bf16) + x fp32->bf16 convert, one launch.
// ---------------------------------------------------------------------------
__global__ __launch_bounds__(256)
void prep_all_kernel(const float* __restrict__ We1, __nv_bfloat16* __restrict__ We1T,
                     const float* __restrict__ We2, __nv_bfloat16* __restrict__ We2T,
                     const float* __restrict__ Wt1, __nv_bfloat16* __restrict__ Wt1T,
                     const float* __restrict__ x,   __nv_bfloat16* __restrict__ xb)
{
    const int bid = blockIdx.x;
    if (bid >= 6528) {
        const int i = (bid - 6528) * 256 + threadIdx.x;
        float4 v = ((const float4*)x)[i];
        __nv_bfloat162* o = (__nv_bfloat162*)xb + (size_t)i * 2;
        o[0] = __floats2bfloat162_rn(v.x, v.y);
        o[1] = __floats2bfloat162_rn(v.z, v.w);
        return;
    }

    __shared__ float t[32][33];
    const float* in;
    __nv_bfloat16* out;
    int K, N, z, ky, nx;
    if (bid < 4096) {                    // We1: z=8, K=1024, N=512
        const int r = bid;
        z = r >> 9; const int tt = r & 511;
        ky = tt >> 4; nx = tt & 15;
        K = ND; N = NH; in = We1; out = We1T;
    } else if (bid < 6144) {             // We2: z=8, K=512, N=512
        const int r = bid - 4096;
        z = r >> 8; const int tt = r & 255;
        ky = tt >> 4; nx = tt & 15;
        K = NH; N = NH; in = We2; out = We2T;
    } else {                             // Wt1: z=3, K=512, N=256
        const int r = bid - 6144;
        z = r >> 7; const int tt = r & 127;
        ky = tt >> 3; nx = tt & 7;
        K = NH; N = NT; in = Wt1; out = Wt1T;
    }
    in  += (size_t)z * K * N;
    out += (size_t)z * K * N;
    const int k0 = ky * 32, n0 = nx * 32;
    const int tx = threadIdx.x & 31, ty = threadIdx.x >> 5;
#pragma unroll
    for (int i = 0; i < 32; i += 8)
        t[ty + i][tx] = in[(size_t)(k0 + ty + i) * N + n0 + tx];
    __syncthreads();
#pragma unroll
    for (int i = 0; i < 32; i += 8)
        out[(size_t)(n0 + ty + i) * K + k0 + tx] = __float2bfloat16_rn(t[tx][ty + i]);
}

// ---------------------------------------------------------------------------
// Gates kernel (forked stream): x.Wg + softmax, 4 rows per thread.
// ---------------------------------------------------------------------------
__global__ __launch_bounds__(256)
void gates_kernel(const float* __restrict__ x, const float* __restrict__ Wg,
                  const float* __restrict__ bg, float* __restrict__ gates)
{
    extern __shared__ float wg_s[];   // [24][WG_PITCH]
    const int tid = threadIdx.x;

    for (int i = tid; i < NTASK * ND * NE / 4; i += 256) {
        const float4 v = ((const float4*)Wg)[i];
        const int base = i * 4;
        const int tt = base / (ND * NE);
        const int r  = base - tt * (ND * NE);
        const int d  = r >> 3;
        const int e0 = r & 7;
        wg_s[(tt * NE + e0 + 0) * WG_PITCH + d] = v.x;
        wg_s[(tt * NE + e0 + 1) * WG_PITCH + d] = v.y;
        wg_s[(tt * NE + e0 + 2) * WG_PITCH + d] = v.z;
        wg_s[(tt * NE + e0 + 3) * WG_PITCH + d] = v.w;
    }
    __syncthreads();

    const int wid = tid >> 5, lane = tid & 31;
    const int b0 = blockIdx.x * 32 + wid * 4;

    const float4* xr0 = (const float4*)(x + (size_t)(b0 + 0) * ND);
    const float4* xr1 = (const float4*)(x + (size_t)(b0 + 1) * ND);
    const float4* xr2 = (const float4*)(x + (size_t)(b0 + 2) * ND);
    const float4* xr3 = (const float4*)(x + (size_t)(b0 + 3) * ND);

    float acc[4][24];
#pragma unroll
    for (int r = 0; r < 4; r++)
#pragma unroll
        for (int te = 0; te < 24; te++) acc[r][te] = 0.f;

#pragma unroll
    for (int i = 0; i < 8; i++) {
        const int d4 = lane + 32 * i;
        float4 xv[4];
        xv[0] = xr0[d4]; xv[1] = xr1[d4]; xv[2] = xr2[d4]; xv[3] = xr3[d4];
#pragma unroll
        for (int te = 0; te < 24; te++) {
            const float4 wv = *(const float4*)(wg_s + te * WG_PITCH + d4 * 4);
#pragma unroll
            for (int r = 0; r < 4; r++) {
                acc[r][te] += xv[r].x * wv.x + xv[r].y * wv.y +
                              xv[r].z * wv.z + xv[r].w * wv.w;
            }
        }
    }
#pragma unroll
    for (int off = 16; off > 0; off >>= 1)
#pragma unroll
        for (int r = 0; r < 4; r++)
#pragma unroll
            for (int te = 0; te < 24; te++)
                acc[r][te] += __shfl_xor_sync(0xffffffffu, acc[r][te], off);

    if (lane < NTASK) {
        const int t = lane;
#pragma unroll
        for (int r = 0; r < 4; r++) {
            float v[NE];
            float mx = -1e30f;
#pragma unroll
            for (int e = 0; e < NE; e++) {
                v[e] = acc[r][t * NE + e] + bg[t * NE + e];
                mx = fmaxf(mx, v[e]);
            }
            float s = 0.f;
#pragma unroll
            for (int e = 0; e < NE; e++) { v[e] = expf(v[e] - mx); s += v[e]; }
            const float inv = 1.f / s;
            float* gout = gates + ((size_t)t * NB + b0 + r) * NE;
#pragma unroll
            for (int e = 0; e < NE; e++) gout[e] = v[e] * inv;
        }
    }
}

// ---------------------------------------------------------------------------
// bf16 tensor-core batched GEMM (expert layers): C = relu(A @ Bt^T + bias)
// CTA tile 128x128, BK=64, 3-stage cp.async, 4 warps, 64x64 warp tiles.
// (Exact R12 structure — best measured configuration.)
// ---------------------------------------------------------------------------
__global__ __launch_bounds__(128, 2)
void gemm_bf16_kernel(const __nv_bfloat16* __restrict__ Ab,
                      const __nv_bfloat16* __restrict__ Bb,
                      const float* __restrict__ biasb, __nv_bfloat16* __restrict__ Cb,
                      int K, int ldc,
                      long long sA, long long sB, long long sBias, long long sC)
{
    extern __shared__ char dynsmem[];
    const uint32_t smb = smem_u32(dynsmem);

    const int z = blockIdx.z;
    const __nv_bfloat16* A  = Ab + (size_t)z * sA + (size_t)(blockIdx.y * TM) * K;
    const __nv_bfloat16* Bt = Bb + (size_t)z * sB + (size_t)(blockIdx.x * TN) * K;
    const float* bias = biasb + (size_t)z * sBias + blockIdx.x * TN;
    __nv_bfloat16* C = Cb + (size_t)z * sC + (size_t)(blockIdx.y * TM) * ldc + blockIdx.x * TN;

    const int tid   = threadIdx.x;
    const int wid   = tid >> 5;
    const int lane  = tid & 31;
    const int gid   = lane >> 2;
    const int tig   = lane & 3;
    const int warpM = wid >> 1;
    const int warpN = wid & 1;

    float* bias_s = (float*)(dynsmem + OFF_BIAS);
    if (tid < TN) bias_s[tid] = bias[tid];

    auto load_stage = [&](int buf, int k0) {
        const __nv_bfloat16* Ag = A + k0;
        const __nv_bfloat16* Bg = Bt + k0;
#pragma unroll
        for (int i = 0; i < 8; i++) {
            const int idx = tid + i * 128;
            const int row = idx >> 3;
            const int c8  = idx & 7;
            const uint32_t off = sw128((uint32_t)(row * 128 + c8 * 16));
            CP_ASYNC16(smb + buf * STAGE_BYTES + off, Ag + (size_t)row * K + c8 * 8);
            CP_ASYNC16(smb + OFF_B + buf * STAGE_BYTES + off, Bg + (size_t)row * K + c8 * 8);
        }
        CP_COMMIT();
    };

    float acc[4][8][4];
#pragma unroll
    for (int mt = 0; mt < 4; mt++)
#pragma unroll
        for (int nt = 0; nt < 8; nt++)
#pragma unroll
            for (int r = 0; r < 4; r++) acc[mt][nt][r] = 0.f;

    const int a_row  = warpM * 64 + (lane & 15);
    const int a_koff = (lane >> 4) * 16;
    const int b_row  = warpN * 64 + (lane & 7) + ((lane >> 4) << 3);
    const int b_koff = ((lane >> 3) & 1) * 16;

    uint32_t af[2][4][4];
    uint32_t bf[2][8][2];

    const int ns = K / BK;
    load_stage(0, 0);
    load_stage(1, BK);

    for (int s = 0; s < ns; s++) {
        if (s + 1 < ns) CP_WAIT1(); else CP_WAIT0();
        __syncthreads();   // single barrier per stage (fences (s+2)%3 reuse too)

        const int buf = s % NSTAGE;
        const uint32_t sa = smb + buf * STAGE_BYTES;
        const uint32_t sb = smb + OFF_B + buf * STAGE_BYTES;

        // fragments for kk=0
#pragma unroll
        for (int mt = 0; mt < 4; mt++) {
            const uint32_t off = (uint32_t)((a_row + mt * 16) * 128 + a_koff);
            ldmatrix_x4(af[0][mt][0], af[0][mt][1], af[0][mt][2], af[0][mt][3],
                        sa + sw128(off));
        }
#pragma unroll
        for (int pr = 0; pr < 4; pr++) {
            const uint32_t off = (uint32_t)((b_row + pr * 16) * 128 + b_koff);
            ldmatrix_x4(bf[0][pr * 2][0], bf[0][pr * 2][1],
                        bf[0][pr * 2 + 1][0], bf[0][pr * 2 + 1][1], sb + sw128(off));
        }

#pragma unroll
        for (int kk = 0; kk < 4; kk++) {
            const int cur = kk & 1;
            const int nxt = cur ^ 1;
            if (kk < 3) {
#pragma unroll
                for (int mt = 0; mt < 4; mt++) {
                    const uint32_t off =
                        (uint32_t)((a_row + mt * 16) * 128 + (kk + 1) * 32 + a_koff);
                    ldmatrix_x4(af[nxt][mt][0], af[nxt][mt][1], af[nxt][mt][2],
                                af[nxt][mt][3], sa + sw128(off));
                }
#pragma unroll
                for (int pr = 0; pr < 4; pr++) {
                    const uint32_t off =
                        (uint32_t)((b_row + pr * 16) * 128 + (kk + 1) * 32 + b_koff);
                    ldmatrix_x4(bf[nxt][pr * 2][0], bf[nxt][pr * 2][1],
                                bf[nxt][pr * 2 + 1][0], bf[nxt][pr * 2 + 1][1],
                                sb + sw128(off));
                }
            }
#pragma unroll
            for (int mt = 0; mt < 4; mt++)
#pragma unroll
                for (int nt = 0; nt < 8; nt++)
                    mma_bf16(acc[mt][nt], af[cur][mt], bf[cur][nt]);
        }
        if (s + 2 < ns) load_stage((s + 2) % NSTAGE, (s + 2) * BK);
    }

    // Epilogue: bias + relu -> bf16
#pragma unroll
    for (int mt = 0; mt < 4; mt++) {
        const int r0 = warpM * 64 + mt * 16 + gid;
#pragma unroll
        for (int nt = 0; nt < 8; nt++) {
            const int c = warpN * 64 + nt * 8 + tig * 2;
            const float2 bv = *(const float2*)(bias_s + c);
            float v0 = fmaxf(acc[mt][nt][0] + bv.x, 0.f);
            float v1 = fmaxf(acc[mt][nt][1] + bv.y, 0.f);
            float v2 = fmaxf(acc[mt][nt][2] + bv.x, 0.f);
            float v3 = fmaxf(acc[mt][nt][3] + bv.y, 0.f);
            *(__nv_bfloat162*)(C + (size_t)r0 * ldc + c) = __floats2bfloat162_rn(v0, v1);
            *(__nv_bfloat162*)(C + (size_t)(r0 + 8) * ldc + c) = __floats2bfloat162_rn(v2, v3);
        }
    }
}

// ---------------------------------------------------------------------------
// Tower GEMM with fused head-partial epilogue. grid = (2, rows/128, NTASK).
// b_off selects the batch half.
// ---------------------------------------------------------------------------
__global__ __launch_bounds__(128, 2)
void tower_gemm_kernel(const __nv_bfloat16* __restrict__ tin,
                       const __nv_bfloat16* __restrict__ Wt1T,
                       const float* __restrict__ bt1,
                       const float* __restrict__ Wt2,
                       float* __restrict__ part, int b_off)
{
    extern __shared__ char dynsmem[];
    const uint32_t smb = smem_u32(dynsmem);
    const int K = NH;

    const int z = blockIdx.z;
    const int brow = b_off + blockIdx.y * TM;
    const __nv_bfloat16* A  = tin + (size_t)z * NB * NH + (size_t)brow * K;
    const __nv_bfloat16* Bt = Wt1T + (size_t)z * NT * NH + (size_t)(blockIdx.x * TN) * K;

    const int tid   = threadIdx.x;
    const int wid   = tid >> 5;
    const int lane  = tid & 31;
    const int gid   = lane >> 2;
    const int tig   = lane & 3;
    const int warpM = wid >> 1;
    const int warpN = wid & 1;

    float* bias_s = (float*)(dynsmem + OFF_BIAS);
    float* w2_s   = (float*)(dynsmem + TW_OFF_W2);
    float* part_s = (float*)(dynsmem + TW_OFF_PART);  // [2][128]
    if (tid < TN) {
        bias_s[tid] = bt1[z * NT + blockIdx.x * TN + tid];
        w2_s[tid]   = Wt2[z * NT + blockIdx.x * TN + tid];
    }

    auto load_stage = [&](int buf, int k0) {
        const __nv_bfloat16* Ag = A + k0;
        const __nv_bfloat16* Bg = Bt + k0;
#pragma unroll
        for (int i = 0; i < 8; i++) {
            const int idx = tid + i * 128;
            const int row = idx >> 3;
            const int c8  = idx & 7;
            const uint32_t off = sw128((uint32_t)(row * 128 + c8 * 16));
            CP_ASYNC16(smb + buf * STAGE_BYTES + off, Ag + (size_t)row * K + c8 * 8);
            CP_ASYNC16(smb + OFF_B + buf * STAGE_BYTES + off, Bg + (size_t)row * K + c8 * 8);
        }
        CP_COMMIT();
    };

    float acc[4][8][4];
#pragma unroll
    for (int mt = 0; mt < 4; mt++)
#pragma unroll
        for (int nt = 0; nt < 8; nt++)
#pragma unroll
            for (int r = 0; r < 4; r++) acc[mt][nt][r] = 0.f;

    const int a_row  = warpM * 64 + (lane & 15);
    const int a_koff = (lane >> 4) * 16;
    const int b_row  = warpN * 64 + (lane & 7) + ((lane >> 4) << 3);
    const int b_koff = ((lane >> 3) & 1) * 16;

    uint32_t af[2][4][4];
    uint32_t bf[2][8][2];

    const int ns = K / BK;      // 8
    load_stage(0, 0);
    load_stage(1, BK);

    for (int s = 0; s < ns; s++) {
        if (s + 1 < ns) CP_WAIT1(); else CP_WAIT0();
        __syncthreads();

        const int buf = s % NSTAGE;
        const uint32_t sa = smb + buf * STAGE_BYTES;
        const uint32_t sb = smb + OFF_B + buf * STAGE_BYTES;

#pragma unroll
        for (int mt = 0; mt < 4; mt++) {
            const uint32_t off = (uint32_t)((a_row + mt * 16) * 128 + a_koff);
            ldmatrix_x4(af[0][mt][0], af[0][mt][1], af[0][mt][2], af[0][mt][3],
                        sa + sw128(off));
        }
#pragma unroll
        for (int pr = 0; pr < 4; pr++) {
            const uint32_t off = (uint32_t)((b_row + pr * 16) * 128 + b_koff);
            ldmatrix_x4(bf[0][pr * 2][0], bf[0][pr * 2][1],
                        bf[0][pr * 2 + 1][0], bf[0][pr * 2 + 1][1], sb + sw128(off));
        }

#pragma unroll
        for (int kk = 0; kk < 4; kk++) {
            const int cur = kk & 1;
            const int nxt = cur ^ 1;
            if (kk < 3) {
#pragma unroll
                for (int mt = 0; mt < 4; mt++) {
                    const uint32_t off =
                        (uint32_t)((a_row + mt * 16) * 128 + (kk + 1) * 32 + a_koff);
                    ldmatrix_x4(af[nxt][mt][0], af[nxt][mt][1], af[nxt][mt][2],
                                af[nxt][mt][3], sa + sw128(off));
                }
#pragma unroll
                for (int pr = 0; pr < 4; pr++) {
                    const uint32_t off =
                        (uint32_t)((b_row + pr * 16) * 128 + (kk + 1) * 32 + b_koff);
                    ldmatrix_x4(bf[nxt][pr * 2][0], bf[nxt][pr * 2][1],
                                bf[nxt][pr * 2 + 1][0], bf[nxt][pr * 2 + 1][1],
                                sb + sw128(off));
                }
            }
#pragma unroll
            for (int mt = 0; mt < 4; mt++)
#pragma unroll
                for (int nt = 0; nt < 8; nt++)
                    mma_bf16(acc[mt][nt], af[cur][mt], bf[cur][nt]);
        }
        if (s + 2 < ns) load_stage((s + 2) % NSTAGE, (s + 2) * BK);
    }

    // Fused head-partial epilogue.
#pragma unroll
    for (int mt = 0; mt < 4; mt++) {
        float p0 = 0.f, p1 = 0.f;
#pragma unroll
        for (int nt = 0; nt < 8; nt++) {
            const int c = warpN * 64 + nt * 8 + tig * 2;
            const float b0 = bias_s[c], b1 = bias_s[c + 1];
            const float w0 = w2_s[c],  w1 = w2_s[c + 1];
            p0 += fmaxf(acc[mt][nt][0] + b0, 0.f) * w0 + fmaxf(acc[mt][nt][1] + b1, 0.f) * w1;
            p1 += fmaxf(acc[mt][nt][2] + b0, 0.f) * w0 + fmaxf(acc[mt][nt][3] + b1, 0.f) * w1;
        }
        p0 += __shfl_xor_sync(0xffffffffu, p0, 1);
        p0 += __shfl_xor_sync(0xffffffffu, p0, 2);
        p1 += __shfl_xor_sync(0xffffffffu, p1, 1);
        p1 += __shfl_xor_sync(0xffffffffu, p1, 2);
        if (tig == 0) {
            const int r = warpM * 64 + mt * 16 + gid;
            part_s[warpN * 128 + r]     = p0;
            part_s[warpN * 128 + r + 8] = p1;
        }
    }
    __syncthreads();
    if (tid < TM) {
        const float v = part_s[tid] + part_s[128 + tid];
        part[((size_t)z * 2 + blockIdx.x) * NB + brow + tid] = v;
    }
}

// ---------------------------------------------------------------------------
// Finalize: out[t,b] = sigmoid(part[t][0][b] + part[t][1][b] + bt2[t])
// ---------------------------------------------------------------------------
__global__ __launch_bounds__(256)
void finalize_kernel(const float* __restrict__ part, const float* __restrict__ bt2,
                     float* __restrict__ out)
{
    const int i = blockIdx.x * 256 + threadIdx.x;   // over NTASK*NB
    if (i >= NTASK * NB) return;
    const int t = i / NB;
    const int b = i - t * NB;
    const float v = part[((size_t)t * 2 + 0) * NB + b] +
                    part[((size_t)t * 2 + 1) * NB + b] + bt2[t];
    out[i] = 1.f / (1.f + expf(-v));
}

// ---------------------------------------------------------------------------
// Combine: tin[t,b,h] = sum_e gates[t,b,e] * eo[e,b,h]  (bf16 in/out)
// b_off selects the batch half; grid covers NBH rows.
// ---------------------------------------------------------------------------
__global__ __launch_bounds__(256)
void combine_kernel(const __nv_bfloat16* __restrict__ eo, const float* __restrict__ gates,
                    __nv_bfloat16* __restrict__ tin, int b_off)
{
    const int idx = blockIdx.x * 256 + threadIdx.x;
    const int h8 = idx & (NH / 8 - 1);
    const int b  = b_off + (idx >> 6);
    if (b >= b_off + NBH) return;

    float g[NTASK][NE];
#pragma unroll
    for (int t = 0; t < NTASK; t++) {
        const float* gp = gates + ((size_t)t * NB + b) * NE;
#pragma unroll
        for (int e = 0; e < NE; e++) g[t][e] = gp[e];
    }

    float o[NTASK][8];
#pragma unroll
    for (int t = 0; t < NTASK; t++)
#pragma unroll
        for (int j = 0; j < 8; j++) o[t][j] = 0.f;

#pragma unroll
    for (int e = 0; e < NE; e++) {
        const __nv_bfloat162* v =
            (const __nv_bfloat162*)(eo + ((size_t)e * NB + b) * NH + h8 * 8);
        float2 f[4];
#pragma unroll
        for (int j = 0; j < 4; j++) f[j] = __bfloat1622float2(v[j]);
#pragma unroll
        for (int t = 0; t < NTASK; t++) {
            const float ge = g[t][e];
#pragma unroll
            for (int j = 0; j < 4; j++) {
                o[t][j * 2 + 0] = fmaf(ge, f[j].x, o[t][j * 2 + 0]);
                o[t][j * 2 + 1] = fmaf(ge, f[j].y, o[t][j * 2 + 1]);
            }
        }
    }
#pragma unroll
    for (int t = 0; t < NTASK; t++) {
        __nv_bfloat162* op = (__nv_bfloat162*)(tin + ((size_t)t * NB + b) * NH + h8 * 8);
#pragma unroll
        for (int j = 0; j < 4; j++)
            op[j] = __floats2bfloat162_rn(o[t][j * 2], o[t][j * 2 + 1]);
    }
}

// ---------------------------------------------------------------------------
// Launch — gates forked; GEMM2/combine/tower split into B-halves so the
// half-0 epilogue chain (DRAM/tensor small kernels) hides under GEMM2 half-1.
// ---------------------------------------------------------------------------
extern "C" void kernel_launch(void* const* d_in, const int* in_sizes, int n_in,
                              void* d_out, int out_size)
{
    const float* x   = (const float*)d_in[0];
    const float* We1 = (const float*)d_in[1];
    const float* be1 = (const float*)d_in[2];
    const float* We2 = (const float*)d_in[3];
    const float* be2 = (const float*)d_in[4];
    const float* Wg  = (const float*)d_in[5];
    const float* bg  = (const float*)d_in[6];
    const float* Wt1 = (const float*)d_in[7];
    const float* bt1 = (const float*)d_in[8];
    const float* Wt2 = (const float*)d_in[9];
    const float* bt2 = (const float*)d_in[10];
    float* out = (float*)d_out;

    __nv_bfloat16 *xb, *h1b, *eob, *tinb, *We1T, *We2T, *Wt1T;
    float *gates, *part;
    cudaGetSymbolAddress((void**)&xb,    g_xb);
    cudaGetSymbolAddress((void**)&h1b,   g_h1b);
    cudaGetSymbolAddress((void**)&eob,   g_eob);
    cudaGetSymbolAddress((void**)&tinb,  g_tinb);
    cudaGetSymbolAddress((void**)&gates, g_gates);
    cudaGetSymbolAddress((void**)&part,  g_part);
    cudaGetSymbolAddress((void**)&We1T,  g_We1T);
    cudaGetSymbolAddress((void**)&We2T,  g_We2T);
    cudaGetSymbolAddress((void**)&Wt1T,  g_Wt1T);

    cudaFuncSetAttribute(gemm_bf16_kernel,
                         cudaFuncAttributeMaxDynamicSharedMemorySize, SMEM_BYTES);
    cudaFuncSetAttribute(tower_gemm_kernel,
                         cudaFuncAttributeMaxDynamicSharedMemorySize, TW_SMEM);
    cudaFuncSetAttribute(gates_kernel,
                         cudaFuncAttributeMaxDynamicSharedMemorySize, GATES_SMEM);

    // Side stream + events (graph-capture-legal fork/join pattern).
    cudaStream_t s2;
    cudaEvent_t ev_fork, ev_gates, ev_g2h0, ev_t0;
    cudaStreamCreateWithFlags(&s2, cudaStreamNonBlocking);
    cudaEventCreateWithFlags(&ev_fork, cudaEventDisableTiming);
    cudaEventCreateWithFlags(&ev_gates, cudaEventDisableTiming);
    cudaEventCreateWithFlags(&ev_g2h0, cudaEventDisableTiming);
    cudaEventCreateWithFlags(&ev_t0, cudaEventDisableTiming);

    cudaEventRecord(ev_fork, 0);
    cudaStreamWaitEvent(s2, ev_fork, 0);

    // Side stream: gate logits + softmax (needed by both combine halves)
    gates_kernel<<<NB / 32, 256, GATES_SMEM, s2>>>(x, Wg, bg, gates);
    cudaEventRecord(ev_gates, s2);

    // Main stream: merged prep (weight transposes + x convert)
    prep_all_kernel<<<6528 + 16384, 256>>>(We1, We1T, We2, We2T, Wt1, Wt1T, x, xb);

    // Expert layer 1 (full batch)
    gemm_bf16_kernel<<<dim3(NH / TN, NB / TM, NE), 128, SMEM_BYTES>>>(
        xb, We1T, be1, h1b, ND, NH,
        0LL, (long long)NH * ND, (long long)NH, (long long)NB * NH);

    // Expert layer 2, batch half 0 (rows [0, NBH))
    gemm_bf16_kernel<<<dim3(NH / TN, NBH / TM, NE), 128, SMEM_BYTES>>>(
        h1b, We2T, be2, eob, NH, NH,
        (long long)NB * NH, (long long)NH * NH, (long long)NH, (long long)NB * NH);
    cudaEventRecord(ev_g2h0, 0);

    // Expert layer 2, batch half 1 (rows [NBH, NB)) — base pointers offset
    gemm_bf16_kernel<<<dim3(NH / TN, NBH / TM, NE), 128, SMEM_BYTES>>>(
        h1b + (size_t)NBH * NH, We2T, be2, eob + (size_t)NBH * NH, NH, NH,
        (long long)NB * NH, (long long)NH * NH, (long long)NH, (long long)NB * NH);

    // Side stream: half-0 epilogue chain overlaps GEMM2 half 1
    cudaStreamWaitEvent(s2, ev_g2h0, 0);
    combine_kernel<<<(NBH * (NH / 8)) / 256, 256, 0, s2>>>(eob, gates, tinb, 0);
    tower_gemm_kernel<<<dim3(NT / TN, NBH / TM, NTASK), 128, TW_SMEM, s2>>>(
        tinb, Wt1T, bt1, Wt2, part, 0);
    cudaEventRecord(ev_t0, s2);

    // Main stream: half-1 epilogue chain (needs gates)
    cudaStreamWaitEvent(0, ev_gates, 0);
    combine_kernel<<<(NBH * (NH / 8)) / 256, 256>>>(eob, gates, tinb, NBH);
    tower_gemm_kernel<<<dim3(NT / TN, NBH / TM, NTASK), 128, TW_SMEM>>>(
        tinb, Wt1T, bt1, Wt2, part, NBH);

    // Join half-0 chain, then finalize (sigmoid) over the full batch
    cudaStreamWaitEvent(0, ev_t0, 0);
    finalize_kernel<<<(NTASK * NB + 255) / 256, 256>>>(part, bt2, out);
}

// round 16
// speedup vs baseline: 1.0702x; 1.0062x over previous
#include <cuda_runtime.h>
#include <cuda_bf16.h>
#include <math.h>
#include <stdint.h>

// Problem constants
#define NB 16384
#define ND 1024
#define NE 8
#define NH 512
#define NT 256
#define NTASK 3
#define NBH (NB / 2)                  // batch half

// GEMM tiling (bf16 mma.sync m16n8k16)
#define TM 128
#define TN 128
#define BK 64
#define NSTAGE 3
#define STAGE_BYTES 16384             // 128 rows x 128 B (64 bf16)
#define OFF_B (NSTAGE * STAGE_BYTES)  // 49152
#define OFF_BIAS (2 * NSTAGE * STAGE_BYTES)   // 98304
#define SMEM_BYTES (OFF_BIAS + 512)   // 98816 -> 2 CTAs/SM

// Tower kernel extra smem (on top of the GEMM layout)
#define TW_OFF_W2   (OFF_BIAS + 512)          // 128 floats
#define TW_OFF_PART (TW_OFF_W2 + 512)         // 2 x 128 floats
#define TW_SMEM     (TW_OFF_PART + 1024)      // 100352 -> still 2 CTAs/SM

// Gates kernel smem: 24 rows x 1032 floats
#define WG_PITCH 1032
#define GATES_SMEM (NTASK * NE * WG_PITCH * 4)

// ---------------------------------------------------------------------------
// Scratch (device globals; no runtime allocation allowed)
// ---------------------------------------------------------------------------
__device__ __nv_bfloat16 g_xb[(size_t)NB * ND];            // x in bf16
__device__ __nv_bfloat16 g_h1b[(size_t)NE * NB * NH];      // [E,B,H] bf16
__device__ __nv_bfloat16 g_eob[(size_t)NE * NB * NH];      // [E,B,H] bf16
__device__ __nv_bfloat16 g_tinb[(size_t)NTASK * NB * NH];  // [T,B,H] bf16
__device__ float g_gates[(size_t)NTASK * NB * NE];         // [T,B,E]
__device__ float g_part[(size_t)NTASK * 2 * NB];           // tower head partials
__device__ __nv_bfloat16 g_We1T[(size_t)NE * NH * ND];     // [E,H,D] bf16 NK
__device__ __nv_bfloat16 g_We2T[(size_t)NE * NH * NH];     // [E,H,H]
__device__ __nv_bfloat16 g_Wt1T[(size_t)NTASK * NT * NH];  // [T,NT,H]

// ---------------------------------------------------------------------------
// Helpers (sm_80-class PTX only)
// ---------------------------------------------------------------------------
__device__ __forceinline__ uint32_t smem_u32(const void* p) {
    uint32_t a;
    asm("{ .reg .u64 t; cvta.to.shared.u64 t, %1; cvt.u32.u64 %0, t; }" : "=r"(a) : "l"(p));
    return a;
}

#define CP_ASYNC16(dst, src) \
    asm volatile("cp.async.cg.shared.global [%0], [%1], 16;" :: "r"(dst), "l"(src))
#define CP_COMMIT() asm volatile("cp.async.commit_group;" ::: "memory")
#define CP_WAIT1()  asm volatile("cp.async.wait_group 1;" ::: "memory")
#define CP_WAIT0()  asm volatile("cp.async.wait_group 0;" ::: "memory")

__device__ __forceinline__ void ldmatrix_x4(uint32_t& r0, uint32_t& r1,
                                            uint32_t& r2, uint32_t& r3, uint32_t addr) {
    asm volatile("ldmatrix.sync.aligned.m8n8.x4.shared.b16 {%0,%1,%2,%3}, [%4];"
                 : "=r"(r0), "=r"(r1), "=r"(r2), "=r"(r3) : "r"(addr));
}

__device__ __forceinline__ void mma_bf16(float (&d)[4], const uint32_t (&a)[4],
                                         const uint32_t (&b)[2]) {
    asm volatile(
        "mma.sync.aligned.m16n8k16.row.col.f32.bf16.bf16.f32 "
        "{%0,%1,%2,%3}, {%4,%5,%6,%7}, {%8,%9}, {%0,%1,%2,%3};"
        : "+f"(d[0]), "+f"(d[1]), "+f"(d[2]), "+f"(d[3])
        : "r"(a[0]), "r"(a[1]), "r"(a[2]), "r"(a[3]), "r"(b[0]), "r"(b[1]));
}

__device__ __forceinline__ uint32_t sw128(uint32_t off) {
    return off ^ ((off >> 3) & 0x70);
}

// ---------------------------------------------------------------------------
// Shared transpose tile body: fp32 [K,N] tile -> bf16 [N,K]
// ---------------------------------------------------------------------------
__device__ __forceinline__ void transpose_tile(const float* in, __nv_bfloat16* out,
                                               int K, int N, int ky, int nx)
{
    __shared__ float t[32][33];
    const int k0 = ky * 32, n0 = nx * 32;
    const int tx = threadIdx.x & 31, ty = threadIdx.x >> 5;
#pragma unroll
    for (int i = 0; i < 32; i += 8)
        t[ty + i][tx] = in[(size_t)(k0 + ty + i) * N + n0 + tx];
    __syncthreads();
#pragma unroll
    for (int i = 0; i < 32; i += 8)
        out[(size_t)(n0 + ty + i) * K + k0 + tx] = __float2bfloat16_rn(t[tx][ty + i]);
}

// ---------------------------------------------------------------------------
// Prep for GEMM1 only: We1 transpose (4096 tiles) + x f2b (16384 blocks).
// ---------------------------------------------------------------------------
__global__ __launch_bounds__(256)
void prep_g1_kernel(const float* __restrict__ We1, __nv_bfloat16* __restrict__ We1T,
                    const float* __restrict__ x,   __nv_bfloat16* __restrict__ xb)
{
    const int bid = blockIdx.x;
    if (bid >= 4096) {
        const int i = (bid - 4096) * 256 + threadIdx.x;
        float4 v = ((const float4*)x)[i];
        __nv_bfloat162* o = (__nv_bfloat162*)xb + (size_t)i * 2;
        o[0] = __floats2bfloat162_rn(v.x, v.y);
        o[1] = __floats2bfloat162_rn(v.z, v.w);
        return;
    }
    // We1: z=8, K=1024, N=512 -> 32x16 tiles per z
    const int z = bid >> 9;
    const int tt = bid & 511;
    transpose_tile(We1 + (size_t)z * ND * NH, We1T + (size_t)z * ND * NH,
                   ND, NH, tt >> 4, tt & 15);
}

// ---------------------------------------------------------------------------
// Prep for GEMM2/tower (side stream): We2 (2048 tiles) + Wt1 (384 tiles).
// ---------------------------------------------------------------------------
__global__ __launch_bounds__(256)
void prep_rest_kernel(const float* __restrict__ We2, __nv_bfloat16* __restrict__ We2T,
                      const float* __restrict__ Wt1, __nv_bfloat16* __restrict__ Wt1T)
{
    const int bid = blockIdx.x;
    if (bid < 2048) {                    // We2: z=8, K=512, N=512 -> 16x16 tiles
        const int z = bid >> 8;
        const int tt = bid & 255;
        transpose_tile(We2 + (size_t)z * NH * NH, We2T + (size_t)z * NH * NH,
                       NH, NH, tt >> 4, tt & 15);
    } else {                             // Wt1: z=3, K=512, N=256 -> 16x8 tiles
        const int r = bid - 2048;
        const int z = r >> 7;
        const int tt = r & 127;
        transpose_tile(Wt1 + (size_t)z * NH * NT, Wt1T + (size_t)z * NH * NT,
                       NH, NT, tt >> 3, tt & 7);
    }
}

// ---------------------------------------------------------------------------
// Gates kernel (forked stream): x.Wg + softmax, 4 rows per thread.
// ---------------------------------------------------------------------------
__global__ __launch_bounds__(256)
void gates_kernel(const float* __restrict__ x, const float* __restrict__ Wg,
                  const float* __restrict__ bg, float* __restrict__ gates)
{
    extern __shared__ float wg_s[];   // [24][WG_PITCH]
    const int tid = threadIdx.x;

    for (int i = tid; i < NTASK * ND * NE / 4; i += 256) {
        const float4 v = ((const float4*)Wg)[i];
        const int base = i * 4;
        const int tt = base / (ND * NE);
        const int r  = base - tt * (ND * NE);
        const int d  = r >> 3;
        const int e0 = r & 7;
        wg_s[(tt * NE + e0 + 0) * WG_PITCH + d] = v.x;
        wg_s[(tt * NE + e0 + 1) * WG_PITCH + d] = v.y;
        wg_s[(tt * NE + e0 + 2) * WG_PITCH + d] = v.z;
        wg_s[(tt * NE + e0 + 3) * WG_PITCH + d] = v.w;
    }
    __syncthreads();

    const int wid = tid >> 5, lane = tid & 31;
    const int b0 = blockIdx.x * 32 + wid * 4;

    const float4* xr0 = (const float4*)(x + (size_t)(b0 + 0) * ND);
    const float4* xr1 = (const float4*)(x + (size_t)(b0 + 1) * ND);
    const float4* xr2 = (const float4*)(x + (size_t)(b0 + 2) * ND);
    const float4* xr3 = (const float4*)(x + (size_t)(b0 + 3) * ND);

    float acc[4][24];
#pragma unroll
    for (int r = 0; r < 4; r++)
#pragma unroll
        for (int te = 0; te < 24; te++) acc[r][te] = 0.f;

#pragma unroll
    for (int i = 0; i < 8; i++) {
        const int d4 = lane + 32 * i;
        float4 xv[4];
        xv[0] = xr0[d4]; xv[1] = xr1[d4]; xv[2] = xr2[d4]; xv[3] = xr3[d4];
#pragma unroll
        for (int te = 0; te < 24; te++) {
            const float4 wv = *(const float4*)(wg_s + te * WG_PITCH + d4 * 4);
#pragma unroll
            for (int r = 0; r < 4; r++) {
                acc[r][te] += xv[r].x * wv.x + xv[r].y * wv.y +
                              xv[r].z * wv.z + xv[r].w * wv.w;
            }
        }
    }
#pragma unroll
    for (int off = 16; off > 0; off >>= 1)
#pragma unroll
        for (int r = 0; r < 4; r++)
#pragma unroll
            for (int te = 0; te < 24; te++)
                acc[r][te] += __shfl_xor_sync(0xffffffffu, acc[r][te], off);

    if (lane < NTASK) {
        const int t = lane;
#pragma unroll
        for (int r = 0; r < 4; r++) {
            float v[NE];
            float mx = -1e30f;
#pragma unroll
            for (int e = 0; e < NE; e++) {
                v[e] = acc[r][t * NE + e] + bg[t * NE + e];
                mx = fmaxf(mx, v[e]);
            }
            float s = 0.f;
#pragma unroll
            for (int e = 0; e < NE; e++) { v[e] = expf(v[e] - mx); s += v[e]; }
            const float inv = 1.f / s;
            float* gout = gates + ((size_t)t * NB + b0 + r) * NE;
#pragma unroll
            for (int e = 0; e < NE; e++) gout[e] = v[e] * inv;
        }
    }
}

// ---------------------------------------------------------------------------
// bf16 tensor-core batched GEMM (expert layers): C = relu(A @ Bt^T + bias)
// CTA tile 128x128, BK=64, 3-stage cp.async, 4 warps, 64x64 warp tiles.
// ---------------------------------------------------------------------------
__global__ __launch_bounds__(128, 2)
void gemm_bf16_kernel(const __nv_bfloat16* __restrict__ Ab,
                      const __nv_bfloat16* __restrict__ Bb,
                      const float* __restrict__ biasb, __nv_bfloat16* __restrict__ Cb,
                      int K, int ldc,
                      long long sA, long long sB, long long sBias, long long sC)
{
    extern __shared__ char dynsmem[];
    const uint32_t smb = smem_u32(dynsmem);

    const int z = blockIdx.z;
    const __nv_bfloat16* A  = Ab + (size_t)z * sA + (size_t)(blockIdx.y * TM) * K;
    const __nv_bfloat16* Bt = Bb + (size_t)z * sB + (size_t)(blockIdx.x * TN) * K;
    const float* bias = biasb + (size_t)z * sBias + blockIdx.x * TN;
    __nv_bfloat16* C = Cb + (size_t)z * sC + (size_t)(blockIdx.y * TM) * ldc + blockIdx.x * TN;

    const int tid   = threadIdx.x;
    const int wid   = tid >> 5;
    const int lane  = tid & 31;
    const int gid   = lane >> 2;
    const int tig   = lane & 3;
    const int warpM = wid >> 1;
    const int warpN = wid & 1;

    float* bias_s = (float*)(dynsmem + OFF_BIAS);
    if (tid < TN) bias_s[tid] = bias[tid];

    auto load_stage = [&](int buf, int k0) {
        const __nv_bfloat16* Ag = A + k0;
        const __nv_bfloat16* Bg = Bt + k0;
#pragma unroll
        for (int i = 0; i < 8; i++) {
            const int idx = tid + i * 128;
            const int row = idx >> 3;
            const int c8  = idx & 7;
            const uint32_t off = sw128((uint32_t)(row * 128 + c8 * 16));
            CP_ASYNC16(smb + buf * STAGE_BYTES + off, Ag + (size_t)row * K + c8 * 8);
            CP_ASYNC16(smb + OFF_B + buf * STAGE_BYTES + off, Bg + (size_t)row * K + c8 * 8);
        }
        CP_COMMIT();
    };

    float acc[4][8][4];
#pragma unroll
    for (int mt = 0; mt < 4; mt++)
#pragma unroll
        for (int nt = 0; nt < 8; nt++)
#pragma unroll
            for (int r = 0; r < 4; r++) acc[mt][nt][r] = 0.f;

    const int a_row  = warpM * 64 + (lane & 15);
    const int a_koff = (lane >> 4) * 16;
    const int b_row  = warpN * 64 + (lane & 7) + ((lane >> 4) << 3);
    const int b_koff = ((lane >> 3) & 1) * 16;

    uint32_t af[2][4][4];
    uint32_t bf[2][8][2];

    const int ns = K / BK;
    load_stage(0, 0);
    load_stage(1, BK);

    for (int s = 0; s < ns; s++) {
        if (s + 1 < ns) CP_WAIT1(); else CP_WAIT0();
        __syncthreads();   // single barrier per stage (fences (s+2)%3 reuse too)

        const int buf = s % NSTAGE;
        const uint32_t sa = smb + buf * STAGE_BYTES;
        const uint32_t sb = smb + OFF_B + buf * STAGE_BYTES;

        // fragments for kk=0
#pragma unroll
        for (int mt = 0; mt < 4; mt++) {
            const uint32_t off = (uint32_t)((a_row + mt * 16) * 128 + a_koff);
            ldmatrix_x4(af[0][mt][0], af[0][mt][1], af[0][mt][2], af[0][mt][3],
                        sa + sw128(off));
        }
#pragma unroll
        for (int pr = 0; pr < 4; pr++) {
            const uint32_t off = (uint32_t)((b_row + pr * 16) * 128 + b_koff);
            ldmatrix_x4(bf[0][pr * 2][0], bf[0][pr * 2][1],
                        bf[0][pr * 2 + 1][0], bf[0][pr * 2 + 1][1], sb + sw128(off));
        }

#pragma unroll
        for (int kk = 0; kk < 4; kk++) {
            const int cur = kk & 1;
            const int nxt = cur ^ 1;
            if (kk < 3) {
#pragma unroll
                for (int mt = 0; mt < 4; mt++) {
                    const uint32_t off =
                        (uint32_t)((a_row + mt * 16) * 128 + (kk + 1) * 32 + a_koff);
                    ldmatrix_x4(af[nxt][mt][0], af[nxt][mt][1], af[nxt][mt][2],
                                af[nxt][mt][3], sa + sw128(off));
                }
#pragma unroll
                for (int pr = 0; pr < 4; pr++) {
                    const uint32_t off =
                        (uint32_t)((b_row + pr * 16) * 128 + (kk + 1) * 32 + b_koff);
                    ldmatrix_x4(bf[nxt][pr * 2][0], bf[nxt][pr * 2][1],
                                bf[nxt][pr * 2 + 1][0], bf[nxt][pr * 2 + 1][1],
                                sb + sw128(off));
                }
            }
#pragma unroll
            for (int mt = 0; mt < 4; mt++)
#pragma unroll
                for (int nt = 0; nt < 8; nt++)
                    mma_bf16(acc[mt][nt], af[cur][mt], bf[cur][nt]);
        }
        if (s + 2 < ns) load_stage((s + 2) % NSTAGE, (s + 2) * BK);
    }

    // Epilogue: bias + relu -> bf16
#pragma unroll
    for (int mt = 0; mt < 4; mt++) {
        const int r0 = warpM * 64 + mt * 16 + gid;
#pragma unroll
        for (int nt = 0; nt < 8; nt++) {
            const int c = warpN * 64 + nt * 8 + tig * 2;
            const float2 bv = *(const float2*)(bias_s + c);
            float v0 = fmaxf(acc[mt][nt][0] + bv.x, 0.f);
            float v1 = fmaxf(acc[mt][nt][1] + bv.y, 0.f);
            float v2 = fmaxf(acc[mt][nt][2] + bv.x, 0.f);
            float v3 = fmaxf(acc[mt][nt][3] + bv.y, 0.f);
            *(__nv_bfloat162*)(C + (size_t)r0 * ldc + c) = __floats2bfloat162_rn(v0, v1);
            *(__nv_bfloat162*)(C + (size_t)(r0 + 8) * ldc + c) = __floats2bfloat162_rn(v2, v3);
        }
    }
}

// ---------------------------------------------------------------------------
// Tower GEMM with fused head-partial epilogue. grid = (2, rows/128, NTASK).
// ---------------------------------------------------------------------------
__global__ __launch_bounds__(128, 2)
void tower_gemm_kernel(const __nv_bfloat16* __restrict__ tin,
                       const __nv_bfloat16* __restrict__ Wt1T,
                       const float* __restrict__ bt1,
                       const float* __restrict__ Wt2,
                       float* __restrict__ part, int b_off)
{
    extern __shared__ char dynsmem[];
    const uint32_t smb = smem_u32(dynsmem);
    const int K = NH;

    const int z = blockIdx.z;
    const int brow = b_off + blockIdx.y * TM;
    const __nv_bfloat16* A  = tin + (size_t)z * NB * NH + (size_t)brow * K;
    const __nv_bfloat16* Bt = Wt1T + (size_t)z * NT * NH + (size_t)(blockIdx.x * TN) * K;

    const int tid   = threadIdx.x;
    const int wid   = tid >> 5;
    const int lane  = tid & 31;
    const int gid   = lane >> 2;
    const int tig   = lane & 3;
    const int warpM = wid >> 1;
    const int warpN = wid & 1;

    float* bias_s = (float*)(dynsmem + OFF_BIAS);
    float* w2_s   = (float*)(dynsmem + TW_OFF_W2);
    float* part_s = (float*)(dynsmem + TW_OFF_PART);  // [2][128]
    if (tid < TN) {
        bias_s[tid] = bt1[z * NT + blockIdx.x * TN + tid];
        w2_s[tid]   = Wt2[z * NT + blockIdx.x * TN + tid];
    }

    auto load_stage = [&](int buf, int k0) {
        const __nv_bfloat16* Ag = A + k0;
        const __nv_bfloat16* Bg = Bt + k0;
#pragma unroll
        for (int i = 0; i < 8; i++) {
            const int idx = tid + i * 128;
            const int row = idx >> 3;
            const int c8  = idx & 7;
            const uint32_t off = sw128((uint32_t)(row * 128 + c8 * 16));
            CP_ASYNC16(smb + buf * STAGE_BYTES + off, Ag + (size_t)row * K + c8 * 8);
            CP_ASYNC16(smb + OFF_B + buf * STAGE_BYTES + off, Bg + (size_t)row * K + c8 * 8);
        }
        CP_COMMIT();
    };

    float acc[4][8][4];
#pragma unroll
    for (int mt = 0; mt < 4; mt++)
#pragma unroll
        for (int nt = 0; nt < 8; nt++)
#pragma unroll
            for (int r = 0; r < 4; r++) acc[mt][nt][r] = 0.f;

    const int a_row  = warpM * 64 + (lane & 15);
    const int a_koff = (lane >> 4) * 16;
    const int b_row  = warpN * 64 + (lane & 7) + ((lane >> 4) << 3);
    const int b_koff = ((lane >> 3) & 1) * 16;

    uint32_t af[2][4][4];
    uint32_t bf[2][8][2];

    const int ns = K / BK;      // 8
    load_stage(0, 0);
    load_stage(1, BK);

    for (int s = 0; s < ns; s++) {
        if (s + 1 < ns) CP_WAIT1(); else CP_WAIT0();
        __syncthreads();

        const int buf = s % NSTAGE;
        const uint32_t sa = smb + buf * STAGE_BYTES;
        const uint32_t sb = smb + OFF_B + buf * STAGE_BYTES;

#pragma unroll
        for (int mt = 0; mt < 4; mt++) {
            const uint32_t off = (uint32_t)((a_row + mt * 16) * 128 + a_koff);
            ldmatrix_x4(af[0][mt][0], af[0][mt][1], af[0][mt][2], af[0][mt][3],
                        sa + sw128(off));
        }
#pragma unroll
        for (int pr = 0; pr < 4; pr++) {
            const uint32_t off = (uint32_t)((b_row + pr * 16) * 128 + b_koff);
            ldmatrix_x4(bf[0][pr * 2][0], bf[0][pr * 2][1],
                        bf[0][pr * 2 + 1][0], bf[0][pr * 2 + 1][1], sb + sw128(off));
        }

#pragma unroll
        for (int kk = 0; kk < 4; kk++) {
            const int cur = kk & 1;
            const int nxt = cur ^ 1;
            if (kk < 3) {
#pragma unroll
                for (int mt = 0; mt < 4; mt++) {
                    const uint32_t off =
                        (uint32_t)((a_row + mt * 16) * 128 + (kk + 1) * 32 + a_koff);
                    ldmatrix_x4(af[nxt][mt][0], af[nxt][mt][1], af[nxt][mt][2],
                                af[nxt][mt][3], sa + sw128(off));
                }
#pragma unroll
                for (int pr = 0; pr < 4; pr++) {
                    const uint32_t off =
                        (uint32_t)((b_row + pr * 16) * 128 + (kk + 1) * 32 + b_koff);
                    ldmatrix_x4(bf[nxt][pr * 2][0], bf[nxt][pr * 2][1],
                                bf[nxt][pr * 2 + 1][0], bf[nxt][pr * 2 + 1][1],
                                sb + sw128(off));
                }
            }
#pragma unroll
            for (int mt = 0; mt < 4; mt++)
#pragma unroll
                for (int nt = 0; nt < 8; nt++)
                    mma_bf16(acc[mt][nt], af[cur][mt], bf[cur][nt]);
        }
        if (s + 2 < ns) load_stage((s + 2) % NSTAGE, (s + 2) * BK);
    }

    // Fused head-partial epilogue.
#pragma unroll
    for (int mt = 0; mt < 4; mt++) {
        float p0 = 0.f, p1 = 0.f;
#pragma unroll
        for (int nt = 0; nt < 8; nt++) {
            const int c = warpN * 64 + nt * 8 + tig * 2;
            const float b0 = bias_s[c], b1 = bias_s[c + 1];
            const float w0 = w2_s[c],  w1 = w2_s[c + 1];
            p0 += fmaxf(acc[mt][nt][0] + b0, 0.f) * w0 + fmaxf(acc[mt][nt][1] + b1, 0.f) * w1;
            p1 += fmaxf(acc[mt][nt][2] + b0, 0.f) * w0 + fmaxf(acc[mt][nt][3] + b1, 0.f) * w1;
        }
        p0 += __shfl_xor_sync(0xffffffffu, p0, 1);
        p0 += __shfl_xor_sync(0xffffffffu, p0, 2);
        p1 += __shfl_xor_sync(0xffffffffu, p1, 1);
        p1 += __shfl_xor_sync(0xffffffffu, p1, 2);
        if (tig == 0) {
            const int r = warpM * 64 + mt * 16 + gid;
            part_s[warpN * 128 + r]     = p0;
            part_s[warpN * 128 + r + 8] = p1;
        }
    }
    __syncthreads();
    if (tid < TM) {
        const float v = part_s[tid] + part_s[128 + tid];
        part[((size_t)z * 2 + blockIdx.x) * NB + brow + tid] = v;
    }
}

// ---------------------------------------------------------------------------
// Finalize: out[t,b] = sigmoid(part[t][0][b] + part[t][1][b] + bt2[t])
// ---------------------------------------------------------------------------
__global__ __launch_bounds__(256)
void finalize_kernel(const float* __restrict__ part, const float* __restrict__ bt2,
                     float* __restrict__ out)
{
    const int i = blockIdx.x * 256 + threadIdx.x;   // over NTASK*NB
    if (i >= NTASK * NB) return;
    const int t = i / NB;
    const int b = i - t * NB;
    const float v = part[((size_t)t * 2 + 0) * NB + b] +
                    part[((size_t)t * 2 + 1) * NB + b] + bt2[t];
    out[i] = 1.f / (1.f + expf(-v));
}

// ---------------------------------------------------------------------------
// Combine: tin[t,b,h] = sum_e gates[t,b,e] * eo[e,b,h]  (bf16 in/out)
// ---------------------------------------------------------------------------
__global__ __launch_bounds__(256)
void combine_kernel(const __nv_bfloat16* __restrict__ eo, const float* __restrict__ gates,
                    __nv_bfloat16* __restrict__ tin, int b_off)
{
    const int idx = blockIdx.x * 256 + threadIdx.x;
    const int h8 = idx & (NH / 8 - 1);
    const int b  = b_off + (idx >> 6);
    if (b >= b_off + NBH) return;

    float g[NTASK][NE];
#pragma unroll
    for (int t = 0; t < NTASK; t++) {
        const float* gp = gates + ((size_t)t * NB + b) * NE;
#pragma unroll
        for (int e = 0; e < NE; e++) g[t][e] = gp[e];
    }

    float o[NTASK][8];
#pragma unroll
    for (int t = 0; t < NTASK; t++)
#pragma unroll
        for (int j = 0; j < 8; j++) o[t][j] = 0.f;

#pragma unroll
    for (int e = 0; e < NE; e++) {
        const __nv_bfloat162* v =
            (const __nv_bfloat162*)(eo + ((size_t)e * NB + b) * NH + h8 * 8);
        float2 f[4];
#pragma unroll
        for (int j = 0; j < 4; j++) f[j] = __bfloat1622float2(v[j]);
#pragma unroll
        for (int t = 0; t < NTASK; t++) {
            const float ge = g[t][e];
#pragma unroll
            for (int j = 0; j < 4; j++) {
                o[t][j * 2 + 0] = fmaf(ge, f[j].x, o[t][j * 2 + 0]);
                o[t][j * 2 + 1] = fmaf(ge, f[j].y, o[t][j * 2 + 1]);
            }
        }
    }
#pragma unroll
    for (int t = 0; t < NTASK; t++) {
        __nv_bfloat162* op = (__nv_bfloat162*)(tin + ((size_t)t * NB + b) * NH + h8 * 8);
#pragma unroll
        for (int j = 0; j < 4; j++)
            op[j] = __floats2bfloat162_rn(o[t][j * 2], o[t][j * 2 + 1]);
    }
}

// ---------------------------------------------------------------------------
// Launch — side stream runs gates + the GEMM2/tower weight prep during
// GEMM1; GEMM2/combine/tower split into B-halves as in R15.
// ---------------------------------------------------------------------------
extern "C" void kernel_launch(void* const* d_in, const int* in_sizes, int n_in,
                              void* d_out, int out_size)
{
    const float* x   = (const float*)d_in[0];
    const float* We1 = (const float*)d_in[1];
    const float* be1 = (const float*)d_in[2];
    const float* We2 = (const float*)d_in[3];
    const float* be2 = (const float*)d_in[4];
    const float* Wg  = (const float*)d_in[5];
    const float* bg  = (const float*)d_in[6];
    const float* Wt1 = (const float*)d_in[7];
    const float* bt1 = (const float*)d_in[8];
    const float* Wt2 = (const float*)d_in[9];
    const float* bt2 = (const float*)d_in[10];
    float* out = (float*)d_out;

    __nv_bfloat16 *xb, *h1b, *eob, *tinb, *We1T, *We2T, *Wt1T;
    float *gates, *part;
    cudaGetSymbolAddress((void**)&xb,    g_xb);
    cudaGetSymbolAddress((void**)&h1b,   g_h1b);
    cudaGetSymbolAddress((void**)&eob,   g_eob);
    cudaGetSymbolAddress((void**)&tinb,  g_tinb);
    cudaGetSymbolAddress((void**)&gates, g_gates);
    cudaGetSymbolAddress((void**)&part,  g_part);
    cudaGetSymbolAddress((void**)&We1T,  g_We1T);
    cudaGetSymbolAddress((void**)&We2T,  g_We2T);
    cudaGetSymbolAddress((void**)&Wt1T,  g_Wt1T);

    cudaFuncSetAttribute(gemm_bf16_kernel,
                         cudaFuncAttributeMaxDynamicSharedMemorySize, SMEM_BYTES);
    cudaFuncSetAttribute(tower_gemm_kernel,
                         cudaFuncAttributeMaxDynamicSharedMemorySize, TW_SMEM);
    cudaFuncSetAttribute(gates_kernel,
                         cudaFuncAttributeMaxDynamicSharedMemorySize, GATES_SMEM);

    // Side stream + events (graph-capture-legal fork/join pattern).
    cudaStream_t s2;
    cudaEvent_t ev_fork, ev_side, ev_g2h0, ev_t0;
    cudaStreamCreateWithFlags(&s2, cudaStreamNonBlocking);
    cudaEventCreateWithFlags(&ev_fork, cudaEventDisableTiming);
    cudaEventCreateWithFlags(&ev_side, cudaEventDisableTiming);
    cudaEventCreateWithFlags(&ev_g2h0, cudaEventDisableTiming);
    cudaEventCreateWithFlags(&ev_t0, cudaEventDisableTiming);

    cudaEventRecord(ev_fork, 0);
    cudaStreamWaitEvent(s2, ev_fork, 0);

    // Side stream: gates + GEMM2/tower weight prep (runs under GEMM1)
    gates_kernel<<<NB / 32, 256, GATES_SMEM, s2>>>(x, Wg, bg, gates);
    prep_rest_kernel<<<2432, 256, 0, s2>>>(We2, We2T, Wt1, Wt1T);
    cudaEventRecord(ev_side, s2);

    // Main stream: GEMM1's own deps only (We1 transpose + x convert)
    prep_g1_kernel<<<4096 + 16384, 256>>>(We1, We1T, x, xb);

    // Expert layer 1 (full batch)
    gemm_bf16_kernel<<<dim3(NH / TN, NB / TM, NE), 128, SMEM_BYTES>>>(
        xb, We1T, be1, h1b, ND, NH,
        0LL, (long long)NH * ND, (long long)NH, (long long)NB * NH);

    // Join side work (gates + We2T + Wt1T) before GEMM2
    cudaStreamWaitEvent(0, ev_side, 0);

    // Expert layer 2, batch half 0 (rows [0, NBH))
    gemm_bf16_kernel<<<dim3(NH / TN, NBH / TM, NE), 128, SMEM_BYTES>>>(
        h1b, We2T, be2, eob, NH, NH,
        (long long)NB * NH, (long long)NH * NH, (long long)NH, (long long)NB * NH);
    cudaEventRecord(ev_g2h0, 0);

    // Expert layer 2, batch half 1 (rows [NBH, NB))
    gemm_bf16_kernel<<<dim3(NH / TN, NBH / TM, NE), 128, SMEM_BYTES>>>(
        h1b + (size_t)NBH * NH, We2T, be2, eob + (size_t)NBH * NH, NH, NH,
        (long long)NB * NH, (long long)NH * NH, (long long)NH, (long long)NB * NH);

    // Side stream: half-0 epilogue chain overlaps GEMM2 half 1
    cudaStreamWaitEvent(s2, ev_g2h0, 0);
    combine_kernel<<<(NBH * (NH / 8)) / 256, 256, 0, s2>>>(eob, gates, tinb, 0);
    tower_gemm_kernel<<<dim3(NT / TN, NBH / TM, NTASK), 128, TW_SMEM, s2>>>(
        tinb, Wt1T, bt1, Wt2, part, 0);
    cudaEventRecord(ev_t0, s2);

    // Main stream: half-1 epilogue chain
    combine_kernel<<<(NBH * (NH / 8)) / 256, 256>>>(eob, gates, tinb, NBH);
    tower_gemm_kernel<<<dim3(NT / TN, NBH / TM, NTASK), 128, TW_SMEM>>>(
        tinb, Wt1T, bt1, Wt2, part, NBH);

    // Join half-0 chain, then finalize (sigmoid) over the full batch
    cudaStreamWaitEvent(0, ev_t0, 0);
    finalize_kernel<<<(NTASK * NB + 255) / 256, 256>>>(part, bt2, out);
}